// round 12
// baseline (speedup 1.0000x reference)
#include <cuda_runtime.h>

#define BB 2
#define CC 64
#define HH 48
#define WWn 48
#define LL 48
#define HWn (HH*WWn)            // 2304
#define SS (HH*WWn*LL)          // 110592
#define GHn 24
#define GSS (GHn*GHn*GHn)       // 13824
#define NSITES (BB*HWn)         // 4608
#define TOTAL (BB*CC*SS)        // 14155776

// ---------------- scratch ----------------
__device__ float g_tx[TOTAL];
__device__ float g_tg[TOTAL];
__device__ float g_tgl[BB*CC*GSS];
__device__ unsigned g_min_p_key;
__device__ unsigned g_min_d_key;
__device__ float g_sitechan[NSITES*CC];
__device__ float g_sitesum[NSITES];
__device__ float g_inv1[BB*CC];
__device__ float g_inv2[BB];

__device__ __forceinline__ unsigned fkey(float f) {
    unsigned u = __float_as_uint(f);
    return (u & 0x80000000u) ? ~u : (u | 0x80000000u);
}
__device__ __forceinline__ float funkey(unsigned k) {
    unsigned u = (k & 0x80000000u) ? (k ^ 0x80000000u) : ~k;
    return __uint_as_float(u);
}

// ---------------- channel-mix GEMM: 128 sites x 64 outs per block ----------
#define CM_SMEM ((64*68 + 64 + 64*132)*4)
__global__ __launch_bounds__(128, 4) void k_chanmix(
        const float* __restrict__ in, const float* __restrict__ Wm,
        const float* __restrict__ bias, int which, int Ssz) {
    extern __shared__ float dyn[];
    float* Wt  = dyn;             // 64*68
    float* bsm = Wt + 64*68;      // 64
    float* Xs  = bsm + 64;        // 64*132
    int tid = threadIdx.x;

    // fold the min-key init into the first kernel (g-side, block (0,0))
    if (which && blockIdx.x == 0 && blockIdx.y == 0 && tid == 0) {
        g_min_p_key = 0xFFFFFFFFu;
        g_min_d_key = 0xFFFFFFFFu;
    }

    for (int i = tid; i < 4096; i += 128) {
        int o = i >> 6, c = i & 63;
        Wt[c*68 + o] = Wm[i];
    }
    if (tid < 64) bsm[tid] = bias[tid];

    int b = blockIdx.y;
    size_t sbase = (size_t)b * CC * Ssz + (size_t)blockIdx.x * 128;
    const float* src = in + sbase;
    for (int i = tid; i < 64*32; i += 128) {
        int c = i >> 5, sv = i & 31;
        float4 v = *(const float4*)(src + (size_t)c*Ssz + sv*4);
        *(float4*)&Xs[c*132 + sv*4] = v;
    }
    __syncthreads();

    int og = tid & 3;
    int sg = tid >> 2;
    float acc[16][4];
#pragma unroll
    for (int j = 0; j < 16; j++) {
        float bv = bsm[og*16 + j];
        acc[j][0]=bv; acc[j][1]=bv; acc[j][2]=bv; acc[j][3]=bv;
    }

#pragma unroll 4
    for (int c = 0; c < 64; c++) {
        float4 xv = *(const float4*)&Xs[c*132 + sg*4];
        float xk[4] = {xv.x, xv.y, xv.z, xv.w};
#pragma unroll
        for (int q = 0; q < 4; q++) {
            float4 wv = *(const float4*)&Wt[c*68 + og*16 + q*4];
            float wk[4] = {wv.x, wv.y, wv.z, wv.w};
#pragma unroll
            for (int jj = 0; jj < 4; jj++)
#pragma unroll
                for (int kk = 0; kk < 4; kk++)
                    acc[q*4+jj][kk] = fmaf(wk[jj], xk[kk], acc[q*4+jj][kk]);
        }
    }

    float* outp = (which ? (float*)g_tgl : (float*)g_tx) + sbase;
#pragma unroll
    for (int j = 0; j < 16; j++) {
        int o = og*16 + j;
        float4 v = make_float4(acc[j][0], acc[j][1], acc[j][2], acc[j][3]);
        *(float4*)(outp + (size_t)o*Ssz + sg*4) = v;
    }
}

// ---------------- trilinear x2 upsample -------------------------------------
__global__ void k_upsample() {
    __shared__ float ph[24*25];
    int h  = blockIdx.x;
    int bc = blockIdx.y;

    int kh = h >> 1;
    int hf = (h & 1) ? (kh+1 > 23 ? 23 : kh+1) : (kh-1 < 0 ? 0 : kh-1);

    const float* bnear = g_tgl + (size_t)bc * GSS + kh*576;
    const float* bfar  = g_tgl + (size_t)bc * GSS + hf*576;
    int tid = threadIdx.y * 24 + threadIdx.x;
    for (int i = tid; i < 576; i += 384) {
        int wi = i / 24, li = i - wi*24;
        ph[wi*25 + li] = 0.75f*bnear[i] + 0.25f*bfar[i];
    }
    __syncthreads();

    int kl = threadIdx.x;
    int lm = kl-1 < 0 ? 0 : kl-1;
    int lp = kl+1 > 23 ? 23 : kl+1;

    float* orow = g_tg + (size_t)bc * SS + (size_t)h * HWn;
    for (int w = threadIdx.y; w < 48; w += 16) {
        int kw = w >> 1;
        int wf = (w & 1) ? (kw+1 > 23 ? 23 : kw+1) : (kw-1 < 0 ? 0 : kw-1);
        const float* rn = &ph[kw*25];
        const float* rf = &ph[wf*25];
        float um = 0.75f*rn[lm] + 0.25f*rf[lm];
        float uc = 0.75f*rn[kl] + 0.25f*rf[kl];
        float up = 0.75f*rn[lp] + 0.25f*rf[lp];
        float2 o;
        o.x = 0.25f*um + 0.75f*uc;
        o.y = 0.75f*uc + 0.25f*up;
        *(float2*)(orow + w*48 + 2*kl) = o;
    }
}

// ---- stats: raw = A*G^T per site (min+sum) AND elementwise tx*tg stats -----
// R11-proven: 256 threads, 2 sites per block; 4x8 tile, interleaved mapping.
#define SD_SMEM (2*2*3328*4)
__global__ __launch_bounds__(256, 3) void k_stats_d() {
    extern __shared__ float dyn[];
    float* Ab = dyn;            // [2][3328]
    float* Gb = dyn + 2*3328;
    __shared__ float pp[256];
    __shared__ float rmin[8], rsum[8], pminw[8];
    int tid = threadIdx.x;

    for (int sj = 0; sj < 2; sj++) {
        int st = blockIdx.x*2 + sj;
        int b = st / HWn, hw = st - b*HWn;
        size_t gb = (size_t)b*CC*SS + (size_t)hw*LL;
        float* As = Ab + sj*3328;
        float* Gs = Gb + sj*3328;
        for (int i = tid; i < 768; i += 256) {
            int c = i / 12, lv = i - c*12;
            size_t off = gb + (size_t)c*SS + lv*4;
            *(float4*)&As[c*52 + lv*4] = *(const float4*)(g_tx + off);
            *(float4*)&Gs[c*52 + lv*4] = *(const float4*)(g_tg + off);
        }
    }
    __syncthreads();

    int sl = tid >> 7;          // site within block
    int s  = tid & 127;         // lane within site group
    const float* As = Ab + sl*3328;
    const float* Gs = Gb + sl*3328;

    // ---- p stats: 2 threads per channel-row, 24 elems each ----
    float pm = 3.402823466e38f;
    {
        int c = s >> 1, hf = s & 1;
        const float* Ar = &As[c*52 + hf*24];
        const float* Gr = &Gs[c*52 + hf*24];
        float ps = 0.f;
#pragma unroll
        for (int q = 0; q < 6; q++) {
            float4 a = *(const float4*)&Ar[q*4];
            float4 g = *(const float4*)&Gr[q*4];
            float t0 = a.x*g.x, t1 = a.y*g.y, t2 = a.z*g.z, t3 = a.w*g.w;
            ps += (t0+t1) + (t2+t3);
            pm = fminf(pm, fminf(fminf(t0,t1), fminf(t2,t3)));
        }
        pp[tid] = ps;
    }
#pragma unroll
    for (int off = 16; off; off >>= 1)
        pm = fminf(pm, __shfl_xor_sync(0xffffffffu, pm, off));
    if ((tid & 31) == 0) pminw[tid >> 5] = pm;

    // ---- raw = A*G^T : 4x8 tile per thread, interleaved mapping ----
    int ti = s >> 3;   // rows i = ti + 16*k, k=0..3
    int tj = s & 7;    // cols j = tj + 8*jj, jj=0..7

    float acc[4][8];
#pragma unroll
    for (int ii = 0; ii < 4; ii++)
#pragma unroll
        for (int jj = 0; jj < 8; jj++) acc[ii][jj] = 0.f;

    for (int l4 = 0; l4 < 12; l4++) {
        float4 av[4];
#pragma unroll
        for (int k = 0; k < 4; k++)
            av[k] = *(const float4*)&As[(ti + 16*k)*52 + l4*4];
#pragma unroll
        for (int jj = 0; jj < 8; jj++) {
            float4 gv = *(const float4*)&Gs[(tj + 8*jj)*52 + l4*4];
#pragma unroll
            for (int k = 0; k < 4; k++) {
                acc[k][jj] = fmaf(av[k].x, gv.x, acc[k][jj]);
                acc[k][jj] = fmaf(av[k].y, gv.y, acc[k][jj]);
                acc[k][jj] = fmaf(av[k].z, gv.z, acc[k][jj]);
                acc[k][jj] = fmaf(av[k].w, gv.w, acc[k][jj]);
            }
        }
    }

    float lmin = acc[0][0], lsum = 0.f;
#pragma unroll
    for (int ii = 0; ii < 4; ii++)
#pragma unroll
        for (int jj = 0; jj < 8; jj++) {
            lmin = fminf(lmin, acc[ii][jj]);
            lsum += acc[ii][jj];
        }
#pragma unroll
    for (int off = 16; off; off >>= 1) {
        lmin = fminf(lmin, __shfl_xor_sync(0xffffffffu, lmin, off));
        lsum += __shfl_xor_sync(0xffffffffu, lsum, off);
    }
    int wid = tid >> 5, lane = tid & 31;
    if (!lane) { rmin[wid] = lmin; rsum[wid] = lsum; }
    __syncthreads();

    // per-(site,channel) p sums: deterministic pairwise combine
    if (s < 64)
        g_sitechan[(size_t)(blockIdx.x*2 + sl)*64 + s] =
            pp[sl*128 + 2*s] + pp[sl*128 + 2*s + 1];

    if (s == 0)   // tid 0 (site 0) and tid 128 (site 1)
        g_sitesum[blockIdx.x*2 + sl] =
            (rsum[sl*4+0] + rsum[sl*4+1]) + (rsum[sl*4+2] + rsum[sl*4+3]);

    if (tid == 0) {
        float m = fminf(fminf(fminf(rmin[0], rmin[1]), fminf(rmin[2], rmin[3])),
                        fminf(fminf(rmin[4], rmin[5]), fminf(rmin[6], rmin[7])));
        atomicMin(&g_min_d_key, fkey(m));
        float pmn = fminf(fminf(fminf(pminw[0], pminw[1]), fminf(pminw[2], pminw[3])),
                          fminf(fminf(pminw[4], pminw[5]), fminf(pminw[6], pminw[7])));
        atomicMin(&g_min_p_key, fkey(pmn));
    }
}

// ------- merged reductions: blocks 0..127 = per-(b,c) p; 128..129 = d -------
__global__ void k_reduce_all() {
    __shared__ float sh[256];
    int tid = threadIdx.x;
    if (blockIdx.x < 128) {
        int bc = blockIdx.x;
        int b = bc >> 6, c = bc & 63;
        float s = 0.f;
        for (int i = tid; i < HWn; i += 256)
            s += g_sitechan[(size_t)(b*HWn + i)*64 + c];
        sh[tid] = s;
        __syncthreads();
        for (int st = 128; st > 0; st >>= 1) {
            if (tid < st) sh[tid] += sh[tid + st];
            __syncthreads();
        }
        if (tid == 0) {
            float m1 = funkey(g_min_p_key);
            g_inv1[bc] = 1.0f / (sh[0] - m1 * (float)SS);
        }
    } else {
        int b = blockIdx.x - 128;
        float s = 0.f;
        for (int i = tid; i < HWn; i += 256) s += g_sitesum[b * HWn + i];
        sh[tid] = s;
        __syncthreads();
        for (int st = 128; st > 0; st >>= 1) {
            if (tid < st) sh[tid] += sh[tid + st];
            __syncthreads();
        }
        if (tid == 0) {
            float m2 = funkey(g_min_d_key);
            g_inv2[b] = 1.0f / (sh[0] - m2 * 9437184.0f);
        }
    }
}

// -------- d (+ fused p): D = (G*(A^T X) - m2*colsum(X))*inv2 ----------------
// 256 threads per site (occupancy retile of R7 shape):
//   phase 1: 3x3 tile/thread; phase 2: 4(j) x 3(l) tile/thread.
#define KD_SMEM ((3328 + 3328 + 3264 + 48)*4)
__global__ __launch_bounds__(256, 4) void k_d(const float* __restrict__ x,
                                              float* __restrict__ outp,
                                              float* __restrict__ outd) {
    extern __shared__ float dyn[];
    float* As = dyn;            // 64*52   (phase1 input; becomes Ms)
    float* Ms = dyn;            // 48*52   overlay
    float* Xs = As + 3328;      // 64*52
    float* Gt = Xs + 3328;      // 48*68 (transposed, swizzled)
    float* cs = Gt + 3264;      // 48
    int tid = threadIdx.x;
    int site = blockIdx.x;
    int b = site / HWn, hw = site - b*HWn;
    size_t gb = (size_t)b*CC*SS + (size_t)hw*LL;

    float m1 = funkey(g_min_p_key);
    for (int i = tid; i < 768; i += 256) {
        int c = i / 12, lv = i - c*12;
        size_t off = gb + (size_t)c*SS + lv*4;
        float4 a  = *(const float4*)(g_tx + off);
        float4 xv = *(const float4*)(x + off);
        float4 gg = *(const float4*)(g_tg + off);
        *(float4*)&As[c*52 + lv*4] = a;
        *(float4*)&Xs[c*52 + lv*4] = xv;
        {
            float gv[4] = {gg.x, gg.y, gg.z, gg.w};
#pragma unroll
            for (int q = 0; q < 4; q++) {
                int row = lv*4 + q;
                int colp = c ^ (8 * ((row >> 3) & 3));
                Gt[row*68 + colp] = gv[q];
            }
        }
        float inv1 = g_inv1[b*64 + c];
        float4 o;
        o.x = (a.x*gg.x - m1) * xv.x * inv1;
        o.y = (a.y*gg.y - m1) * xv.y * inv1;
        o.z = (a.z*gg.z - m1) * xv.z * inv1;
        o.w = (a.w*gg.w - m1) * xv.w * inv1;
        *(float4*)(outp + off) = o;
    }
    __syncthreads();

    if (tid < 48) {
        float s = 0.f;
#pragma unroll 8
        for (int c = 0; c < 64; c++) s += Xs[c*52 + tid];
        cs[tid] = s;
    }

    // phase 1: M[lp][l] = sum_c A[c][lp] * X[c][l]; 3x3 tile per thread
    float p1acc[3][3];
    int p1ti = tid >> 4;   // lp = p1ti*3 + ii  (0..47)
    int p1tj = tid & 15;   // l  = p1tj*3 + jj  (0..47)
    {
#pragma unroll
        for (int ii = 0; ii < 3; ii++)
#pragma unroll
            for (int jj = 0; jj < 3; jj++) p1acc[ii][jj] = 0.f;

#pragma unroll 4
        for (int c = 0; c < 64; c++) {
            float a0 = As[c*52 + p1ti*3 + 0];
            float a1 = As[c*52 + p1ti*3 + 1];
            float a2 = As[c*52 + p1ti*3 + 2];
            float x0 = Xs[c*52 + p1tj*3 + 0];
            float x1 = Xs[c*52 + p1tj*3 + 1];
            float x2 = Xs[c*52 + p1tj*3 + 2];
            p1acc[0][0] = fmaf(a0, x0, p1acc[0][0]);
            p1acc[0][1] = fmaf(a0, x1, p1acc[0][1]);
            p1acc[0][2] = fmaf(a0, x2, p1acc[0][2]);
            p1acc[1][0] = fmaf(a1, x0, p1acc[1][0]);
            p1acc[1][1] = fmaf(a1, x1, p1acc[1][1]);
            p1acc[1][2] = fmaf(a1, x2, p1acc[1][2]);
            p1acc[2][0] = fmaf(a2, x0, p1acc[2][0]);
            p1acc[2][1] = fmaf(a2, x1, p1acc[2][1]);
            p1acc[2][2] = fmaf(a2, x2, p1acc[2][2]);
        }
    }
    __syncthreads();   // all As reads done -> safe to overlay Ms

#pragma unroll
    for (int ii = 0; ii < 3; ii++)
#pragma unroll
        for (int jj = 0; jj < 3; jj++)
            Ms[(p1ti*3+ii)*52 + p1tj*3 + jj] = p1acc[ii][jj];
    __syncthreads();

    // phase 2: D[j][l] = sum_lp Gt[lp][j] * M[lp][l]; 4(j) x 3(l) per thread
    float m2  = funkey(g_min_d_key);
    float inv = g_inv2[b];
    {
        int ti = tid >> 4;   // j = ti*4 + k, k=0..3  (0..63)
        int tj = tid & 15;   // l = tj*3 + m
        float acc[4][3];
#pragma unroll
        for (int k = 0; k < 4; k++)
#pragma unroll
            for (int m = 0; m < 3; m++) acc[k][m] = 0.f;

#pragma unroll 4
        for (int lp = 0; lp < 48; lp++) {
            int jbase = (ti*4) ^ (8 * ((lp >> 3) & 3));
            float4 gA = *(const float4*)&Gt[lp*68 + jbase];
            float gk[4] = {gA.x, gA.y, gA.z, gA.w};
            float q0 = Ms[lp*52 + tj*3 + 0];
            float q1 = Ms[lp*52 + tj*3 + 1];
            float q2 = Ms[lp*52 + tj*3 + 2];
#pragma unroll
            for (int k = 0; k < 4; k++) {
                acc[k][0] = fmaf(gk[k], q0, acc[k][0]);
                acc[k][1] = fmaf(gk[k], q1, acc[k][1]);
                acc[k][2] = fmaf(gk[k], q2, acc[k][2]);
            }
        }

        float cc0 = cs[tj*3+0], cc1 = cs[tj*3+1], cc2 = cs[tj*3+2];
#pragma unroll
        for (int k = 0; k < 4; k++) {
            int j = ti*4 + k;
            size_t ob = gb + (size_t)j*SS + tj*3;
            outd[ob+0] = (acc[k][0] - m2*cc0) * inv;
            outd[ob+1] = (acc[k][1] - m2*cc1) * inv;
            outd[ob+2] = (acc[k][2] - m2*cc2) * inv;
        }
    }
}

// ---------------- launch ----------------------------------------------------
extern "C" void kernel_launch(void* const* d_in, const int* in_sizes, int n_in,
                              void* d_out, int out_size) {
    const float* x  = (const float*)d_in[0];
    const float* g  = (const float*)d_in[1];
    const float* W1 = (const float*)d_in[2];
    const float* b1 = (const float*)d_in[3];
    const float* W2 = (const float*)d_in[4];
    const float* b2 = (const float*)d_in[5];

    float* out  = (float*)d_out;
    float* outp = out;
    float* outd = out + (size_t)TOTAL;

    cudaFuncSetAttribute(k_chanmix, cudaFuncAttributeMaxDynamicSharedMemorySize, CM_SMEM);
    cudaFuncSetAttribute(k_stats_d, cudaFuncAttributeMaxDynamicSharedMemorySize, SD_SMEM);
    cudaFuncSetAttribute(k_d,       cudaFuncAttributeMaxDynamicSharedMemorySize, KD_SMEM);

    { dim3 gg(GSS/128, BB); k_chanmix<<<gg, 128, CM_SMEM>>>(g, W2, b2, 1, GSS); }
    { dim3 gx(SS/128,  BB); k_chanmix<<<gx, 128, CM_SMEM>>>(x, W1, b1, 0, SS); }
    { dim3 gu(HH, BB*CC);   k_upsample<<<gu, dim3(24, 16)>>>(); }

    k_stats_d<<<NSITES/2, 256, SD_SMEM>>>();
    k_reduce_all<<<130, 256>>>();

    k_d<<<NSITES, 256, KD_SMEM>>>(x, outp, outd);
}

// round 13
// speedup vs baseline: 1.0515x; 1.0515x over previous
#include <cuda_runtime.h>

#define BB 2
#define CC 64
#define HH 48
#define WWn 48
#define LL 48
#define HWn (HH*WWn)            // 2304
#define SS (HH*WWn*LL)          // 110592
#define GHn 24
#define GSS (GHn*GHn*GHn)       // 13824
#define NSITES (BB*HWn)         // 4608
#define TOTAL (BB*CC*SS)        // 14155776

// ---------------- scratch ----------------
__device__ float g_tx[TOTAL];
__device__ float g_tg[TOTAL];
__device__ float g_tgl[BB*CC*GSS];
__device__ unsigned g_min_p_key;
__device__ unsigned g_min_d_key;
__device__ float g_sitechan[NSITES*CC];
__device__ float g_sitesum[NSITES];
__device__ float g_inv1[BB*CC];
__device__ float g_inv2[BB];

__device__ __forceinline__ unsigned fkey(float f) {
    unsigned u = __float_as_uint(f);
    return (u & 0x80000000u) ? ~u : (u | 0x80000000u);
}
__device__ __forceinline__ float funkey(unsigned k) {
    unsigned u = (k & 0x80000000u) ? (k ^ 0x80000000u) : ~k;
    return __uint_as_float(u);
}

// ---------------- channel-mix GEMM: 128 sites x 64 outs per block ----------
#define CM_SMEM ((64*68 + 64 + 64*132)*4)
__global__ __launch_bounds__(128, 4) void k_chanmix(
        const float* __restrict__ in, const float* __restrict__ Wm,
        const float* __restrict__ bias, int which, int Ssz) {
    extern __shared__ float dyn[];
    float* Wt  = dyn;             // 64*68
    float* bsm = Wt + 64*68;      // 64
    float* Xs  = bsm + 64;        // 64*132
    int tid = threadIdx.x;

    // fold the min-key init into the first kernel (g-side, block (0,0))
    if (which && blockIdx.x == 0 && blockIdx.y == 0 && tid == 0) {
        g_min_p_key = 0xFFFFFFFFu;
        g_min_d_key = 0xFFFFFFFFu;
    }

    for (int i = tid; i < 4096; i += 128) {
        int o = i >> 6, c = i & 63;
        Wt[c*68 + o] = Wm[i];
    }
    if (tid < 64) bsm[tid] = bias[tid];

    int b = blockIdx.y;
    size_t sbase = (size_t)b * CC * Ssz + (size_t)blockIdx.x * 128;
    const float* src = in + sbase;
    for (int i = tid; i < 64*32; i += 128) {
        int c = i >> 5, sv = i & 31;
        float4 v = *(const float4*)(src + (size_t)c*Ssz + sv*4);
        *(float4*)&Xs[c*132 + sv*4] = v;
    }
    __syncthreads();

    int og = tid & 3;
    int sg = tid >> 2;
    float acc[16][4];
#pragma unroll
    for (int j = 0; j < 16; j++) {
        float bv = bsm[og*16 + j];
        acc[j][0]=bv; acc[j][1]=bv; acc[j][2]=bv; acc[j][3]=bv;
    }

#pragma unroll 4
    for (int c = 0; c < 64; c++) {
        float4 xv = *(const float4*)&Xs[c*132 + sg*4];
        float xk[4] = {xv.x, xv.y, xv.z, xv.w};
#pragma unroll
        for (int q = 0; q < 4; q++) {
            float4 wv = *(const float4*)&Wt[c*68 + og*16 + q*4];
            float wk[4] = {wv.x, wv.y, wv.z, wv.w};
#pragma unroll
            for (int jj = 0; jj < 4; jj++)
#pragma unroll
                for (int kk = 0; kk < 4; kk++)
                    acc[q*4+jj][kk] = fmaf(wk[jj], xk[kk], acc[q*4+jj][kk]);
        }
    }

    float* outp = (which ? (float*)g_tgl : (float*)g_tx) + sbase;
#pragma unroll
    for (int j = 0; j < 16; j++) {
        int o = og*16 + j;
        float4 v = make_float4(acc[j][0], acc[j][1], acc[j][2], acc[j][3]);
        *(float4*)(outp + (size_t)o*Ssz + sg*4) = v;
    }
}

// ---- stats + fused trilinear upsample of theta_g ---------------------------
// 256 threads, 2 sites per block; per site: stage hw-interp row R[c][24]
// (padded [26] for l-clamp) from L2-resident g_tgl, synthesize G on the fly,
// write G to g_tg (k_d consumes), run p-stats + raw=A*G^T (4x8 interleaved).
#define SD_SMEM ((2*2*3328 + 2*64*26)*4)
__global__ __launch_bounds__(256, 3) void k_stats_d() {
    extern __shared__ float dyn[];
    float* Ab = dyn;                 // [2][3328]
    float* Gb = dyn + 2*3328;        // [2][3328]
    float* Rs = dyn + 4*3328;        // [2][64*26]
    __shared__ float pp[256];
    __shared__ float rmin[8], rsum[8], pminw[8];
    int tid = threadIdx.x;

    // ---- stage 1: hw-interpolated low-res rows R (exact upsample arith) ----
#pragma unroll
    for (int sj = 0; sj < 2; sj++) {
        int st = blockIdx.x*2 + sj;
        int b = st / HWn, hw = st - b*HWn;
        int h = hw / 48, w = hw - h*48;
        int kh = h >> 1, kw = w >> 1;
        int hf = (h & 1) ? (kh+1 > 23 ? 23 : kh+1) : (kh-1 < 0 ? 0 : kh-1);
        int wf = (w & 1) ? (kw+1 > 23 ? 23 : kw+1) : (kw-1 < 0 ? 0 : kw-1);
        const float* base = g_tgl + (size_t)b*CC*GSS;
        int o_nn = kh*576 + kw*24;
        int o_fn = hf*576 + kw*24;
        int o_nw = kh*576 + wf*24;
        int o_fw = hf*576 + wf*24;
        float* R = Rs + sj*(64*26);
        for (int i = tid; i < 384; i += 256) {
            int c = i / 6, q = i - c*6;
            const float* pc = base + (size_t)c*GSS + q*4;
            float4 a  = *(const float4*)(pc + o_nn);
            float4 bv = *(const float4*)(pc + o_fn);
            float4 cv = *(const float4*)(pc + o_nw);
            float4 dv = *(const float4*)(pc + o_fw);
            float r0 = 0.75f*(0.75f*a.x + 0.25f*bv.x) + 0.25f*(0.75f*cv.x + 0.25f*dv.x);
            float r1 = 0.75f*(0.75f*a.y + 0.25f*bv.y) + 0.25f*(0.75f*cv.y + 0.25f*dv.y);
            float r2 = 0.75f*(0.75f*a.z + 0.25f*bv.z) + 0.25f*(0.75f*cv.z + 0.25f*dv.z);
            float r3 = 0.75f*(0.75f*a.w + 0.25f*bv.w) + 0.25f*(0.75f*cv.w + 0.25f*dv.w);
            int idx = c*26 + 1 + q*4;
            R[idx+0] = r0; R[idx+1] = r1; R[idx+2] = r2; R[idx+3] = r3;
            if (q == 0) R[c*26]      = r0;   // l-clamp low
            if (q == 5) R[c*26 + 25] = r3;   // l-clamp high
        }
    }
    __syncthreads();

    // ---- stage 2: load A, synthesize G (l-interp), write g_tg, fill tiles --
#pragma unroll
    for (int sj = 0; sj < 2; sj++) {
        int st = blockIdx.x*2 + sj;
        int b = st / HWn, hw = st - b*HWn;
        size_t gb = (size_t)b*CC*SS + (size_t)hw*LL;
        float* As = Ab + sj*3328;
        float* Gs = Gb + sj*3328;
        const float* R = Rs + sj*(64*26);
        for (int i = tid; i < 768; i += 256) {
            int c = i / 12, lv = i - c*12;
            size_t off = gb + (size_t)c*SS + lv*4;
            *(float4*)&As[c*52 + lv*4] = *(const float4*)(g_tx + off);
            const float* Rr = R + c*26 + 2*lv;
            float2 r01 = *(const float2*)(Rr);       // R[2lv-1], R[2lv]
            float2 r23 = *(const float2*)(Rr + 2);   // R[2lv+1], R[2lv+2]
            float4 gg;
            gg.x = 0.25f*r01.x + 0.75f*r01.y;
            gg.y = 0.75f*r01.y + 0.25f*r23.x;
            gg.z = 0.25f*r01.y + 0.75f*r23.x;
            gg.w = 0.75f*r23.x + 0.25f*r23.y;
            *(float4*)&Gs[c*52 + lv*4] = gg;
            *(float4*)(g_tg + off) = gg;
        }
    }
    __syncthreads();

    int sl = tid >> 7;          // site within block
    int s  = tid & 127;         // lane within site group
    const float* As = Ab + sl*3328;
    const float* Gs = Gb + sl*3328;

    // ---- p stats: 2 threads per channel-row, 24 elems each ----
    float pm = 3.402823466e38f;
    {
        int c = s >> 1, hf = s & 1;
        const float* Ar = &As[c*52 + hf*24];
        const float* Gr = &Gs[c*52 + hf*24];
        float ps = 0.f;
#pragma unroll
        for (int q = 0; q < 6; q++) {
            float4 a = *(const float4*)&Ar[q*4];
            float4 g = *(const float4*)&Gr[q*4];
            float t0 = a.x*g.x, t1 = a.y*g.y, t2 = a.z*g.z, t3 = a.w*g.w;
            ps += (t0+t1) + (t2+t3);
            pm = fminf(pm, fminf(fminf(t0,t1), fminf(t2,t3)));
        }
        pp[tid] = ps;
    }
#pragma unroll
    for (int off = 16; off; off >>= 1)
        pm = fminf(pm, __shfl_xor_sync(0xffffffffu, pm, off));
    if ((tid & 31) == 0) pminw[tid >> 5] = pm;

    // ---- raw = A*G^T : 4x8 tile per thread, interleaved mapping ----
    int ti = s >> 3;   // rows i = ti + 16*k, k=0..3
    int tj = s & 7;    // cols j = tj + 8*jj, jj=0..7

    float acc[4][8];
#pragma unroll
    for (int ii = 0; ii < 4; ii++)
#pragma unroll
        for (int jj = 0; jj < 8; jj++) acc[ii][jj] = 0.f;

    for (int l4 = 0; l4 < 12; l4++) {
        float4 av[4];
#pragma unroll
        for (int k = 0; k < 4; k++)
            av[k] = *(const float4*)&As[(ti + 16*k)*52 + l4*4];
#pragma unroll
        for (int jj = 0; jj < 8; jj++) {
            float4 gv = *(const float4*)&Gs[(tj + 8*jj)*52 + l4*4];
#pragma unroll
            for (int k = 0; k < 4; k++) {
                acc[k][jj] = fmaf(av[k].x, gv.x, acc[k][jj]);
                acc[k][jj] = fmaf(av[k].y, gv.y, acc[k][jj]);
                acc[k][jj] = fmaf(av[k].z, gv.z, acc[k][jj]);
                acc[k][jj] = fmaf(av[k].w, gv.w, acc[k][jj]);
            }
        }
    }

    float lmin = acc[0][0], lsum = 0.f;
#pragma unroll
    for (int ii = 0; ii < 4; ii++)
#pragma unroll
        for (int jj = 0; jj < 8; jj++) {
            lmin = fminf(lmin, acc[ii][jj]);
            lsum += acc[ii][jj];
        }
#pragma unroll
    for (int off = 16; off; off >>= 1) {
        lmin = fminf(lmin, __shfl_xor_sync(0xffffffffu, lmin, off));
        lsum += __shfl_xor_sync(0xffffffffu, lsum, off);
    }
    int wid = tid >> 5, lane = tid & 31;
    if (!lane) { rmin[wid] = lmin; rsum[wid] = lsum; }
    __syncthreads();

    // per-(site,channel) p sums: deterministic pairwise combine
    if (s < 64)
        g_sitechan[(size_t)(blockIdx.x*2 + sl)*64 + s] =
            pp[sl*128 + 2*s] + pp[sl*128 + 2*s + 1];

    if (s == 0)   // tid 0 (site 0) and tid 128 (site 1)
        g_sitesum[blockIdx.x*2 + sl] =
            (rsum[sl*4+0] + rsum[sl*4+1]) + (rsum[sl*4+2] + rsum[sl*4+3]);

    if (tid == 0) {
        float m = fminf(fminf(fminf(rmin[0], rmin[1]), fminf(rmin[2], rmin[3])),
                        fminf(fminf(rmin[4], rmin[5]), fminf(rmin[6], rmin[7])));
        atomicMin(&g_min_d_key, fkey(m));
        float pmn = fminf(fminf(fminf(pminw[0], pminw[1]), fminf(pminw[2], pminw[3])),
                          fminf(fminf(pminw[4], pminw[5]), fminf(pminw[6], pminw[7])));
        atomicMin(&g_min_p_key, fkey(pmn));
    }
}

// ------- merged reductions: blocks 0..127 = per-(b,c) p; 128..129 = d -------
__global__ void k_reduce_all() {
    __shared__ float sh[256];
    int tid = threadIdx.x;
    if (blockIdx.x < 128) {
        int bc = blockIdx.x;
        int b = bc >> 6, c = bc & 63;
        float s = 0.f;
        for (int i = tid; i < HWn; i += 256)
            s += g_sitechan[(size_t)(b*HWn + i)*64 + c];
        sh[tid] = s;
        __syncthreads();
        for (int st = 128; st > 0; st >>= 1) {
            if (tid < st) sh[tid] += sh[tid + st];
            __syncthreads();
        }
        if (tid == 0) {
            float m1 = funkey(g_min_p_key);
            g_inv1[bc] = 1.0f / (sh[0] - m1 * (float)SS);
        }
    } else {
        int b = blockIdx.x - 128;
        float s = 0.f;
        for (int i = tid; i < HWn; i += 256) s += g_sitesum[b * HWn + i];
        sh[tid] = s;
        __syncthreads();
        for (int st = 128; st > 0; st >>= 1) {
            if (tid < st) sh[tid] += sh[tid + st];
            __syncthreads();
        }
        if (tid == 0) {
            float m2 = funkey(g_min_d_key);
            g_inv2[b] = 1.0f / (sh[0] - m2 * 9437184.0f);
        }
    }
}

// -------- d (+ fused p): D = (G*(A^T X) - m2*colsum(X))*inv2 ----------------
// R7/R11-exact proven configuration (128 threads, occ 5).
#define KD_SMEM ((3328 + 3328 + 3264 + 48)*4)
__global__ __launch_bounds__(128, 5) void k_d(const float* __restrict__ x,
                                              float* __restrict__ outp,
                                              float* __restrict__ outd) {
    extern __shared__ float dyn[];
    float* As = dyn;            // 64*52   (phase1 input; becomes Ms)
    float* Ms = dyn;            // 48*52   overlay
    float* Xs = As + 3328;      // 64*52
    float* Gt = Xs + 3328;      // 48*68 (transposed, swizzled)
    float* cs = Gt + 3264;      // 48
    int tid = threadIdx.x;
    int site = blockIdx.x;
    int b = site / HWn, hw = site - b*HWn;
    size_t gb = (size_t)b*CC*SS + (size_t)hw*LL;

    float m1 = funkey(g_min_p_key);
    for (int i = tid; i < 64*12; i += 128) {
        int c = i / 12, lv = i - c*12;
        size_t off = gb + (size_t)c*SS + lv*4;
        float4 a  = *(const float4*)(g_tx + off);
        float4 xv = *(const float4*)(x + off);
        float4 gg = *(const float4*)(g_tg + off);
        *(float4*)&As[c*52 + lv*4] = a;
        *(float4*)&Xs[c*52 + lv*4] = xv;
        {
            float gv[4] = {gg.x, gg.y, gg.z, gg.w};
#pragma unroll
            for (int q = 0; q < 4; q++) {
                int row = lv*4 + q;
                int colp = c ^ (8 * ((row >> 3) & 3));
                Gt[row*68 + colp] = gv[q];
            }
        }
        float inv1 = g_inv1[b*64 + c];
        float4 o;
        o.x = (a.x*gg.x - m1) * xv.x * inv1;
        o.y = (a.y*gg.y - m1) * xv.y * inv1;
        o.z = (a.z*gg.z - m1) * xv.z * inv1;
        o.w = (a.w*gg.w - m1) * xv.w * inv1;
        *(float4*)(outp + off) = o;
    }
    __syncthreads();

    if (tid < 48) {
        float s = 0.f;
#pragma unroll 8
        for (int c = 0; c < 64; c++) s += Xs[c*52 + tid];
        cs[tid] = s;
    }

    // phase 1: M[lp][l] = sum_c A[c][lp] * X[c][l] (accumulate in registers)
    float p1acc[3][6];
    int p1ti = tid >> 3;
    int p1tj = tid & 7;
    {
#pragma unroll
        for (int ii = 0; ii < 3; ii++)
#pragma unroll
            for (int jj = 0; jj < 6; jj++) p1acc[ii][jj] = 0.f;

#pragma unroll 4
        for (int c = 0; c < 64; c++) {
            float a0 = As[c*52 + p1ti*3 + 0];
            float a1 = As[c*52 + p1ti*3 + 1];
            float a2 = As[c*52 + p1ti*3 + 2];
            float xv[6];
#pragma unroll
            for (int jj = 0; jj < 6; jj++) xv[jj] = Xs[c*52 + p1tj*6 + jj];
#pragma unroll
            for (int jj = 0; jj < 6; jj++) {
                p1acc[0][jj] = fmaf(a0, xv[jj], p1acc[0][jj]);
                p1acc[1][jj] = fmaf(a1, xv[jj], p1acc[1][jj]);
                p1acc[2][jj] = fmaf(a2, xv[jj], p1acc[2][jj]);
            }
        }
    }
    __syncthreads();   // all As reads done -> safe to overlay Ms

#pragma unroll
    for (int ii = 0; ii < 3; ii++)
#pragma unroll
        for (int jj = 0; jj < 6; jj++)
            Ms[(p1ti*3+ii)*52 + p1tj*6 + jj] = p1acc[ii][jj];
    __syncthreads();

    // phase 2: D[j][l] = sum_lp Gt[lp][j] * M[lp][l]
    float m2  = funkey(g_min_d_key);
    float inv = g_inv2[b];
    {
        int ti = tid >> 4;
        int tj = tid & 15;
        float acc[8][3];
#pragma unroll
        for (int k = 0; k < 8; k++)
#pragma unroll
            for (int m = 0; m < 3; m++) acc[k][m] = 0.f;

#pragma unroll 4
        for (int lp = 0; lp < 48; lp++) {
            int jbase = (ti*8) ^ (8 * ((lp >> 3) & 3));
            float4 gA = *(const float4*)&Gt[lp*68 + jbase];
            float4 gB = *(const float4*)&Gt[lp*68 + jbase + 4];
            float gk[8] = {gA.x,gA.y,gA.z,gA.w,gB.x,gB.y,gB.z,gB.w};
            float q0 = Ms[lp*52 + tj*3 + 0];
            float q1 = Ms[lp*52 + tj*3 + 1];
            float q2 = Ms[lp*52 + tj*3 + 2];
#pragma unroll
            for (int k = 0; k < 8; k++) {
                acc[k][0] = fmaf(gk[k], q0, acc[k][0]);
                acc[k][1] = fmaf(gk[k], q1, acc[k][1]);
                acc[k][2] = fmaf(gk[k], q2, acc[k][2]);
            }
        }

        float cc0 = cs[tj*3+0], cc1 = cs[tj*3+1], cc2 = cs[tj*3+2];
#pragma unroll
        for (int k = 0; k < 8; k++) {
            int j = ti*8 + k;
            size_t ob = gb + (size_t)j*SS + tj*3;
            outd[ob+0] = (acc[k][0] - m2*cc0) * inv;
            outd[ob+1] = (acc[k][1] - m2*cc1) * inv;
            outd[ob+2] = (acc[k][2] - m2*cc2) * inv;
        }
    }
}

// ---------------- launch ----------------------------------------------------
extern "C" void kernel_launch(void* const* d_in, const int* in_sizes, int n_in,
                              void* d_out, int out_size) {
    const float* x  = (const float*)d_in[0];
    const float* g  = (const float*)d_in[1];
    const float* W1 = (const float*)d_in[2];
    const float* b1 = (const float*)d_in[3];
    const float* W2 = (const float*)d_in[4];
    const float* b2 = (const float*)d_in[5];

    float* out  = (float*)d_out;
    float* outp = out;
    float* outd = out + (size_t)TOTAL;

    cudaFuncSetAttribute(k_chanmix, cudaFuncAttributeMaxDynamicSharedMemorySize, CM_SMEM);
    cudaFuncSetAttribute(k_stats_d, cudaFuncAttributeMaxDynamicSharedMemorySize, SD_SMEM);
    cudaFuncSetAttribute(k_d,       cudaFuncAttributeMaxDynamicSharedMemorySize, KD_SMEM);

    { dim3 gg(GSS/128, BB); k_chanmix<<<gg, 128, CM_SMEM>>>(g, W2, b2, 1, GSS); }
    { dim3 gx(SS/128,  BB); k_chanmix<<<gx, 128, CM_SMEM>>>(x, W1, b1, 0, SS); }

    k_stats_d<<<NSITES/2, 256, SD_SMEM>>>();
    k_reduce_all<<<130, 256>>>();

    k_d<<<NSITES, 128, KD_SMEM>>>(x, outp, outd);
}

// round 14
// speedup vs baseline: 1.0634x; 1.0113x over previous
#include <cuda_runtime.h>

#define BB 2
#define CC 64
#define HH 48
#define WWn 48
#define LL 48
#define HWn (HH*WWn)            // 2304
#define SS (HH*WWn*LL)          // 110592
#define GHn 24
#define GSS (GHn*GHn*GHn)       // 13824
#define NSITES (BB*HWn)         // 4608
#define TOTAL (BB*CC*SS)        // 14155776

// ---------------- scratch ----------------
__device__ float g_tx[TOTAL];
__device__ float g_tg[TOTAL];
__device__ float g_tgl[BB*CC*GSS];
__device__ unsigned g_min_p_key;
__device__ unsigned g_min_d_key;
__device__ float g_sitechan[BB*CC*HWn];   // [bc][site-hw] transposed layout
__device__ float g_sitesum[NSITES];
__device__ float g_inv1[BB*CC];
__device__ float g_inv2[BB];

__device__ __forceinline__ unsigned fkey(float f) {
    unsigned u = __float_as_uint(f);
    return (u & 0x80000000u) ? ~u : (u | 0x80000000u);
}
__device__ __forceinline__ float funkey(unsigned k) {
    unsigned u = (k & 0x80000000u) ? (k ^ 0x80000000u) : ~k;
    return __uint_as_float(u);
}

// ---------------- channel-mix GEMM: 128 sites x 64 outs per block ----------
#define CM_SMEM ((64*68 + 64 + 64*132)*4)
__global__ __launch_bounds__(128, 4) void k_chanmix(
        const float* __restrict__ in, const float* __restrict__ Wm,
        const float* __restrict__ bias, int which, int Ssz) {
    extern __shared__ float dyn[];
    float* Wt  = dyn;             // 64*68
    float* bsm = Wt + 64*68;      // 64
    float* Xs  = bsm + 64;        // 64*132
    int tid = threadIdx.x;

    // fold the min-key init into the first kernel (g-side, block (0,0))
    if (which && blockIdx.x == 0 && blockIdx.y == 0 && tid == 0) {
        g_min_p_key = 0xFFFFFFFFu;
        g_min_d_key = 0xFFFFFFFFu;
    }

    for (int i = tid; i < 4096; i += 128) {
        int o = i >> 6, c = i & 63;
        Wt[c*68 + o] = Wm[i];
    }
    if (tid < 64) bsm[tid] = bias[tid];

    int b = blockIdx.y;
    size_t sbase = (size_t)b * CC * Ssz + (size_t)blockIdx.x * 128;
    const float* src = in + sbase;
    for (int i = tid; i < 64*32; i += 128) {
        int c = i >> 5, sv = i & 31;
        float4 v = *(const float4*)(src + (size_t)c*Ssz + sv*4);
        *(float4*)&Xs[c*132 + sv*4] = v;
    }
    __syncthreads();

    int og = tid & 3;
    int sg = tid >> 2;
    float acc[16][4];
#pragma unroll
    for (int j = 0; j < 16; j++) {
        float bv = bsm[og*16 + j];
        acc[j][0]=bv; acc[j][1]=bv; acc[j][2]=bv; acc[j][3]=bv;
    }

#pragma unroll 4
    for (int c = 0; c < 64; c++) {
        float4 xv = *(const float4*)&Xs[c*132 + sg*4];
        float xk[4] = {xv.x, xv.y, xv.z, xv.w};
#pragma unroll
        for (int q = 0; q < 4; q++) {
            float4 wv = *(const float4*)&Wt[c*68 + og*16 + q*4];
            float wk[4] = {wv.x, wv.y, wv.z, wv.w};
#pragma unroll
            for (int jj = 0; jj < 4; jj++)
#pragma unroll
                for (int kk = 0; kk < 4; kk++)
                    acc[q*4+jj][kk] = fmaf(wk[jj], xk[kk], acc[q*4+jj][kk]);
        }
    }

    float* outp = (which ? (float*)g_tgl : (float*)g_tx) + sbase;
#pragma unroll
    for (int j = 0; j < 16; j++) {
        int o = og*16 + j;
        float4 v = make_float4(acc[j][0], acc[j][1], acc[j][2], acc[j][3]);
        *(float4*)(outp + (size_t)o*Ssz + sg*4) = v;
    }
}

// ---- stats + fused trilinear upsample of theta_g ---------------------------
#define SD_SMEM ((2*2*3328 + 2*64*26)*4)
__global__ __launch_bounds__(256, 3) void k_stats_d() {
    extern __shared__ float dyn[];
    float* Ab = dyn;                 // [2][3328]
    float* Gb = dyn + 2*3328;        // [2][3328]
    float* Rs = dyn + 4*3328;        // [2][64*26]
    __shared__ float pp[256];
    __shared__ float rmin[8], rsum[8], pminw[8];
    int tid = threadIdx.x;

    // ---- stage 1: hw-interpolated low-res rows R (exact upsample arith) ----
#pragma unroll
    for (int sj = 0; sj < 2; sj++) {
        int st = blockIdx.x*2 + sj;
        int b = st / HWn, hw = st - b*HWn;
        int h = hw / 48, w = hw - h*48;
        int kh = h >> 1, kw = w >> 1;
        int hf = (h & 1) ? (kh+1 > 23 ? 23 : kh+1) : (kh-1 < 0 ? 0 : kh-1);
        int wf = (w & 1) ? (kw+1 > 23 ? 23 : kw+1) : (kw-1 < 0 ? 0 : kw-1);
        const float* base = g_tgl + (size_t)b*CC*GSS;
        int o_nn = kh*576 + kw*24;
        int o_fn = hf*576 + kw*24;
        int o_nw = kh*576 + wf*24;
        int o_fw = hf*576 + wf*24;
        float* R = Rs + sj*(64*26);
        for (int i = tid; i < 384; i += 256) {
            int c = i / 6, q = i - c*6;
            const float* pc = base + (size_t)c*GSS + q*4;
            float4 a  = *(const float4*)(pc + o_nn);
            float4 bv = *(const float4*)(pc + o_fn);
            float4 cv = *(const float4*)(pc + o_nw);
            float4 dv = *(const float4*)(pc + o_fw);
            float r0 = 0.75f*(0.75f*a.x + 0.25f*bv.x) + 0.25f*(0.75f*cv.x + 0.25f*dv.x);
            float r1 = 0.75f*(0.75f*a.y + 0.25f*bv.y) + 0.25f*(0.75f*cv.y + 0.25f*dv.y);
            float r2 = 0.75f*(0.75f*a.z + 0.25f*bv.z) + 0.25f*(0.75f*cv.z + 0.25f*dv.z);
            float r3 = 0.75f*(0.75f*a.w + 0.25f*bv.w) + 0.25f*(0.75f*cv.w + 0.25f*dv.w);
            int idx = c*26 + 1 + q*4;
            R[idx+0] = r0; R[idx+1] = r1; R[idx+2] = r2; R[idx+3] = r3;
            if (q == 0) R[c*26]      = r0;   // l-clamp low
            if (q == 5) R[c*26 + 25] = r3;   // l-clamp high
        }
    }
    __syncthreads();

    // ---- stage 2: load A, synthesize G (l-interp), write g_tg, fill tiles --
#pragma unroll
    for (int sj = 0; sj < 2; sj++) {
        int st = blockIdx.x*2 + sj;
        int b = st / HWn, hw = st - b*HWn;
        size_t gb = (size_t)b*CC*SS + (size_t)hw*LL;
        float* As = Ab + sj*3328;
        float* Gs = Gb + sj*3328;
        const float* R = Rs + sj*(64*26);
        for (int i = tid; i < 768; i += 256) {
            int c = i / 12, lv = i - c*12;
            size_t off = gb + (size_t)c*SS + lv*4;
            *(float4*)&As[c*52 + lv*4] = *(const float4*)(g_tx + off);
            const float* Rr = R + c*26 + 2*lv;
            float2 r01 = *(const float2*)(Rr);       // R[2lv-1], R[2lv]
            float2 r23 = *(const float2*)(Rr + 2);   // R[2lv+1], R[2lv+2]
            float4 gg;
            gg.x = 0.25f*r01.x + 0.75f*r01.y;
            gg.y = 0.75f*r01.y + 0.25f*r23.x;
            gg.z = 0.25f*r01.y + 0.75f*r23.x;
            gg.w = 0.75f*r23.x + 0.25f*r23.y;
            *(float4*)&Gs[c*52 + lv*4] = gg;
            *(float4*)(g_tg + off) = gg;
        }
    }
    __syncthreads();

    int sl = tid >> 7;          // site within block
    int s  = tid & 127;         // lane within site group
    const float* As = Ab + sl*3328;
    const float* Gs = Gb + sl*3328;

    // ---- p stats: 2 threads per channel-row, 24 elems each ----
    float pm = 3.402823466e38f;
    {
        int c = s >> 1, hf = s & 1;
        const float* Ar = &As[c*52 + hf*24];
        const float* Gr = &Gs[c*52 + hf*24];
        float ps = 0.f;
#pragma unroll
        for (int q = 0; q < 6; q++) {
            float4 a = *(const float4*)&Ar[q*4];
            float4 g = *(const float4*)&Gr[q*4];
            float t0 = a.x*g.x, t1 = a.y*g.y, t2 = a.z*g.z, t3 = a.w*g.w;
            ps += (t0+t1) + (t2+t3);
            pm = fminf(pm, fminf(fminf(t0,t1), fminf(t2,t3)));
        }
        pp[tid] = ps;
    }
#pragma unroll
    for (int off = 16; off; off >>= 1)
        pm = fminf(pm, __shfl_xor_sync(0xffffffffu, pm, off));
    if ((tid & 31) == 0) pminw[tid >> 5] = pm;

    // ---- raw = A*G^T : 4x8 tile per thread, interleaved mapping ----
    int ti = s >> 3;   // rows i = ti + 16*k, k=0..3
    int tj = s & 7;    // cols j = tj + 8*jj, jj=0..7

    float acc[4][8];
#pragma unroll
    for (int ii = 0; ii < 4; ii++)
#pragma unroll
        for (int jj = 0; jj < 8; jj++) acc[ii][jj] = 0.f;

    for (int l4 = 0; l4 < 12; l4++) {
        float4 av[4];
#pragma unroll
        for (int k = 0; k < 4; k++)
            av[k] = *(const float4*)&As[(ti + 16*k)*52 + l4*4];
#pragma unroll
        for (int jj = 0; jj < 8; jj++) {
            float4 gv = *(const float4*)&Gs[(tj + 8*jj)*52 + l4*4];
#pragma unroll
            for (int k = 0; k < 4; k++) {
                acc[k][jj] = fmaf(av[k].x, gv.x, acc[k][jj]);
                acc[k][jj] = fmaf(av[k].y, gv.y, acc[k][jj]);
                acc[k][jj] = fmaf(av[k].z, gv.z, acc[k][jj]);
                acc[k][jj] = fmaf(av[k].w, gv.w, acc[k][jj]);
            }
        }
    }

    float lmin = acc[0][0], lsum = 0.f;
#pragma unroll
    for (int ii = 0; ii < 4; ii++)
#pragma unroll
        for (int jj = 0; jj < 8; jj++) {
            lmin = fminf(lmin, acc[ii][jj]);
            lsum += acc[ii][jj];
        }
#pragma unroll
    for (int off = 16; off; off >>= 1) {
        lmin = fminf(lmin, __shfl_xor_sync(0xffffffffu, lmin, off));
        lsum += __shfl_xor_sync(0xffffffffu, lsum, off);
    }
    int wid = tid >> 5, lane = tid & 31;
    if (!lane) { rmin[wid] = lmin; rsum[wid] = lsum; }
    __syncthreads();

    // per-(b,c) p sums, transposed layout [bc][hw] for coalesced reduce
    if (s < 64) {
        int st = blockIdx.x*2 + sl;
        int b = st / HWn, hw = st - b*HWn;
        g_sitechan[(size_t)(b*64 + s)*HWn + hw] =
            pp[sl*128 + 2*s] + pp[sl*128 + 2*s + 1];
    }

    if (s == 0)   // tid 0 (site 0) and tid 128 (site 1)
        g_sitesum[blockIdx.x*2 + sl] =
            (rsum[sl*4+0] + rsum[sl*4+1]) + (rsum[sl*4+2] + rsum[sl*4+3]);

    if (tid == 0) {
        float m = fminf(fminf(fminf(rmin[0], rmin[1]), fminf(rmin[2], rmin[3])),
                        fminf(fminf(rmin[4], rmin[5]), fminf(rmin[6], rmin[7])));
        atomicMin(&g_min_d_key, fkey(m));
        float pmn = fminf(fminf(fminf(pminw[0], pminw[1]), fminf(pminw[2], pminw[3])),
                          fminf(fminf(pminw[4], pminw[5]), fminf(pminw[6], pminw[7])));
        atomicMin(&g_min_p_key, fkey(pmn));
    }
}

// ------- merged reductions: blocks 0..127 = per-(b,c) p; 128..129 = d -------
__global__ void k_reduce_all() {
    __shared__ float sh[256];
    int tid = threadIdx.x;
    if (blockIdx.x < 128) {
        int bc = blockIdx.x;
        const float* row = g_sitechan + (size_t)bc * HWn;
        float s = 0.f;
        for (int i = tid; i < HWn; i += 256)   // coalesced
            s += row[i];
        sh[tid] = s;
        __syncthreads();
        for (int st = 128; st > 0; st >>= 1) {
            if (tid < st) sh[tid] += sh[tid + st];
            __syncthreads();
        }
        if (tid == 0) {
            float m1 = funkey(g_min_p_key);
            g_inv1[bc] = 1.0f / (sh[0] - m1 * (float)SS);
        }
    } else {
        int b = blockIdx.x - 128;
        float s = 0.f;
        for (int i = tid; i < HWn; i += 256) s += g_sitesum[b * HWn + i];
        sh[tid] = s;
        __syncthreads();
        for (int st = 128; st > 0; st >>= 1) {
            if (tid < st) sh[tid] += sh[tid + st];
            __syncthreads();
        }
        if (tid == 0) {
            float m2 = funkey(g_min_d_key);
            g_inv2[b] = 1.0f / (sh[0] - m2 * 9437184.0f);
        }
    }
}

// -------- d (+ fused p): D = (G*(A^T X) - m2*colsum(X))*inv2 ----------------
// R7/R11-exact shape; streaming hints: __ldcs on final-use reads, __stcs on
// outputs (preserve L2 residency of g_tx/g_tg for later blocks).
#define KD_SMEM ((3328 + 3328 + 3264 + 48)*4)
__global__ __launch_bounds__(128, 5) void k_d(const float* __restrict__ x,
                                              float* __restrict__ outp,
                                              float* __restrict__ outd) {
    extern __shared__ float dyn[];
    float* As = dyn;            // 64*52   (phase1 input; becomes Ms)
    float* Ms = dyn;            // 48*52   overlay
    float* Xs = As + 3328;      // 64*52
    float* Gt = Xs + 3328;      // 48*68 (transposed, swizzled)
    float* cs = Gt + 3264;      // 48
    int tid = threadIdx.x;
    int site = blockIdx.x;
    int b = site / HWn, hw = site - b*HWn;
    size_t gb = (size_t)b*CC*SS + (size_t)hw*LL;

    float m1 = funkey(g_min_p_key);
    for (int i = tid; i < 64*12; i += 128) {
        int c = i / 12, lv = i - c*12;
        size_t off = gb + (size_t)c*SS + lv*4;
        float4 a  = __ldcs((const float4*)(g_tx + off));
        float4 xv = __ldcs((const float4*)(x + off));
        float4 gg = __ldcs((const float4*)(g_tg + off));
        *(float4*)&As[c*52 + lv*4] = a;
        *(float4*)&Xs[c*52 + lv*4] = xv;
        {
            float gv[4] = {gg.x, gg.y, gg.z, gg.w};
#pragma unroll
            for (int q = 0; q < 4; q++) {
                int row = lv*4 + q;
                int colp = c ^ (8 * ((row >> 3) & 3));
                Gt[row*68 + colp] = gv[q];
            }
        }
        float inv1 = g_inv1[b*64 + c];
        float4 o;
        o.x = (a.x*gg.x - m1) * xv.x * inv1;
        o.y = (a.y*gg.y - m1) * xv.y * inv1;
        o.z = (a.z*gg.z - m1) * xv.z * inv1;
        o.w = (a.w*gg.w - m1) * xv.w * inv1;
        __stcs((float4*)(outp + off), o);
    }
    __syncthreads();

    if (tid < 48) {
        float s = 0.f;
#pragma unroll 8
        for (int c = 0; c < 64; c++) s += Xs[c*52 + tid];
        cs[tid] = s;
    }

    // phase 1: M[lp][l] = sum_c A[c][lp] * X[c][l] (accumulate in registers)
    float p1acc[3][6];
    int p1ti = tid >> 3;
    int p1tj = tid & 7;
    {
#pragma unroll
        for (int ii = 0; ii < 3; ii++)
#pragma unroll
            for (int jj = 0; jj < 6; jj++) p1acc[ii][jj] = 0.f;

#pragma unroll 4
        for (int c = 0; c < 64; c++) {
            float a0 = As[c*52 + p1ti*3 + 0];
            float a1 = As[c*52 + p1ti*3 + 1];
            float a2 = As[c*52 + p1ti*3 + 2];
            float xv[6];
#pragma unroll
            for (int jj = 0; jj < 6; jj++) xv[jj] = Xs[c*52 + p1tj*6 + jj];
#pragma unroll
            for (int jj = 0; jj < 6; jj++) {
                p1acc[0][jj] = fmaf(a0, xv[jj], p1acc[0][jj]);
                p1acc[1][jj] = fmaf(a1, xv[jj], p1acc[1][jj]);
                p1acc[2][jj] = fmaf(a2, xv[jj], p1acc[2][jj]);
            }
        }
    }
    __syncthreads();   // all As reads done -> safe to overlay Ms

#pragma unroll
    for (int ii = 0; ii < 3; ii++)
#pragma unroll
        for (int jj = 0; jj < 6; jj++)
            Ms[(p1ti*3+ii)*52 + p1tj*6 + jj] = p1acc[ii][jj];
    __syncthreads();

    // phase 2: D[j][l] = sum_lp Gt[lp][j] * M[lp][l]
    float m2  = funkey(g_min_d_key);
    float inv = g_inv2[b];
    {
        int ti = tid >> 4;
        int tj = tid & 15;
        float acc[8][3];
#pragma unroll
        for (int k = 0; k < 8; k++)
#pragma unroll
            for (int m = 0; m < 3; m++) acc[k][m] = 0.f;

#pragma unroll 4
        for (int lp = 0; lp < 48; lp++) {
            int jbase = (ti*8) ^ (8 * ((lp >> 3) & 3));
            float4 gA = *(const float4*)&Gt[lp*68 + jbase];
            float4 gB = *(const float4*)&Gt[lp*68 + jbase + 4];
            float gk[8] = {gA.x,gA.y,gA.z,gA.w,gB.x,gB.y,gB.z,gB.w};
            float q0 = Ms[lp*52 + tj*3 + 0];
            float q1 = Ms[lp*52 + tj*3 + 1];
            float q2 = Ms[lp*52 + tj*3 + 2];
#pragma unroll
            for (int k = 0; k < 8; k++) {
                acc[k][0] = fmaf(gk[k], q0, acc[k][0]);
                acc[k][1] = fmaf(gk[k], q1, acc[k][1]);
                acc[k][2] = fmaf(gk[k], q2, acc[k][2]);
            }
        }

        float cc0 = cs[tj*3+0], cc1 = cs[tj*3+1], cc2 = cs[tj*3+2];
#pragma unroll
        for (int k = 0; k < 8; k++) {
            int j = ti*8 + k;
            size_t ob = gb + (size_t)j*SS + tj*3;
            __stcs(outd + ob + 0, (acc[k][0] - m2*cc0) * inv);
            __stcs(outd + ob + 1, (acc[k][1] - m2*cc1) * inv);
            __stcs(outd + ob + 2, (acc[k][2] - m2*cc2) * inv);
        }
    }
}

// ---------------- launch ----------------------------------------------------
extern "C" void kernel_launch(void* const* d_in, const int* in_sizes, int n_in,
                              void* d_out, int out_size) {
    const float* x  = (const float*)d_in[0];
    const float* g  = (const float*)d_in[1];
    const float* W1 = (const float*)d_in[2];
    const float* b1 = (const float*)d_in[3];
    const float* W2 = (const float*)d_in[4];
    const float* b2 = (const float*)d_in[5];

    float* out  = (float*)d_out;
    float* outp = out;
    float* outd = out + (size_t)TOTAL;

    cudaFuncSetAttribute(k_chanmix, cudaFuncAttributeMaxDynamicSharedMemorySize, CM_SMEM);
    cudaFuncSetAttribute(k_stats_d, cudaFuncAttributeMaxDynamicSharedMemorySize, SD_SMEM);
    cudaFuncSetAttribute(k_d,       cudaFuncAttributeMaxDynamicSharedMemorySize, KD_SMEM);

    { dim3 gg(GSS/128, BB); k_chanmix<<<gg, 128, CM_SMEM>>>(g, W2, b2, 1, GSS); }
    { dim3 gx(SS/128,  BB); k_chanmix<<<gx, 128, CM_SMEM>>>(x, W1, b1, 0, SS); }

    k_stats_d<<<NSITES/2, 256, SD_SMEM>>>();
    k_reduce_all<<<130, 256>>>();

    k_d<<<NSITES, 128, KD_SMEM>>>(x, outp, outd);
}

// round 15
// speedup vs baseline: 1.0694x; 1.0056x over previous
#include <cuda_runtime.h>

#define BB 2
#define CC 64
#define HH 48
#define WWn 48
#define LL 48
#define HWn (HH*WWn)            // 2304
#define SS (HH*WWn*LL)          // 110592
#define GHn 24
#define GSS (GHn*GHn*GHn)       // 13824
#define NSITES (BB*HWn)         // 4608
#define TOTAL (BB*CC*SS)        // 14155776

// ---------------- scratch ----------------
__device__ float g_tx[TOTAL];
__device__ float g_tgl[BB*CC*GSS];
__device__ unsigned g_min_p_key;
__device__ unsigned g_min_d_key;
__device__ float g_sitechan[BB*CC*HWn];   // [bc][site-hw] transposed layout
__device__ float g_sitesum[NSITES];
__device__ float g_inv1[BB*CC];
__device__ float g_inv2[BB];

__device__ __forceinline__ unsigned fkey(float f) {
    unsigned u = __float_as_uint(f);
    return (u & 0x80000000u) ? ~u : (u | 0x80000000u);
}
__device__ __forceinline__ float funkey(unsigned k) {
    unsigned u = (k & 0x80000000u) ? (k ^ 0x80000000u) : ~k;
    return __uint_as_float(u);
}

// ---------------- channel-mix GEMM: 128 sites x 64 outs per block ----------
#define CM_SMEM ((64*68 + 64 + 64*132)*4)
__global__ __launch_bounds__(128, 4) void k_chanmix(
        const float* __restrict__ in, const float* __restrict__ Wm,
        const float* __restrict__ bias, int which, int Ssz) {
    extern __shared__ float dyn[];
    float* Wt  = dyn;             // 64*68
    float* bsm = Wt + 64*68;      // 64
    float* Xs  = bsm + 64;        // 64*132
    int tid = threadIdx.x;

    // fold the min-key init into the first kernel (g-side, block (0,0))
    if (which && blockIdx.x == 0 && blockIdx.y == 0 && tid == 0) {
        g_min_p_key = 0xFFFFFFFFu;
        g_min_d_key = 0xFFFFFFFFu;
    }

    for (int i = tid; i < 4096; i += 128) {
        int o = i >> 6, c = i & 63;
        Wt[c*68 + o] = Wm[i];
    }
    if (tid < 64) bsm[tid] = bias[tid];

    int b = blockIdx.y;
    size_t sbase = (size_t)b * CC * Ssz + (size_t)blockIdx.x * 128;
    const float* src = in + sbase;
    for (int i = tid; i < 64*32; i += 128) {
        int c = i >> 5, sv = i & 31;
        float4 v = *(const float4*)(src + (size_t)c*Ssz + sv*4);
        *(float4*)&Xs[c*132 + sv*4] = v;
    }
    __syncthreads();

    int og = tid & 3;
    int sg = tid >> 2;
    float acc[16][4];
#pragma unroll
    for (int j = 0; j < 16; j++) {
        float bv = bsm[og*16 + j];
        acc[j][0]=bv; acc[j][1]=bv; acc[j][2]=bv; acc[j][3]=bv;
    }

#pragma unroll 4
    for (int c = 0; c < 64; c++) {
        float4 xv = *(const float4*)&Xs[c*132 + sg*4];
        float xk[4] = {xv.x, xv.y, xv.z, xv.w};
#pragma unroll
        for (int q = 0; q < 4; q++) {
            float4 wv = *(const float4*)&Wt[c*68 + og*16 + q*4];
            float wk[4] = {wv.x, wv.y, wv.z, wv.w};
#pragma unroll
            for (int jj = 0; jj < 4; jj++)
#pragma unroll
                for (int kk = 0; kk < 4; kk++)
                    acc[q*4+jj][kk] = fmaf(wk[jj], xk[kk], acc[q*4+jj][kk]);
        }
    }

    float* outp = (which ? (float*)g_tgl : (float*)g_tx) + sbase;
#pragma unroll
    for (int j = 0; j < 16; j++) {
        int o = og*16 + j;
        float4 v = make_float4(acc[j][0], acc[j][1], acc[j][2], acc[j][3]);
        *(float4*)(outp + (size_t)o*Ssz + sg*4) = v;
    }
}

// ---- stats + fused trilinear upsample of theta_g (no g_tg materialized) ----
#define SD_SMEM ((2*2*3328 + 2*64*26)*4)
__global__ __launch_bounds__(256, 3) void k_stats_d() {
    extern __shared__ float dyn[];
    float* Ab = dyn;                 // [2][3328]
    float* Gb = dyn + 2*3328;        // [2][3328]
    float* Rs = dyn + 4*3328;        // [2][64*26]
    __shared__ float pp[256];
    __shared__ float rmin[8], rsum[8], pminw[8];
    int tid = threadIdx.x;

    // ---- stage 1: hw-interpolated low-res rows R (exact upsample arith) ----
#pragma unroll
    for (int sj = 0; sj < 2; sj++) {
        int st = blockIdx.x*2 + sj;
        int b = st / HWn, hw = st - b*HWn;
        int h = hw / 48, w = hw - h*48;
        int kh = h >> 1, kw = w >> 1;
        int hf = (h & 1) ? (kh+1 > 23 ? 23 : kh+1) : (kh-1 < 0 ? 0 : kh-1);
        int wf = (w & 1) ? (kw+1 > 23 ? 23 : kw+1) : (kw-1 < 0 ? 0 : kw-1);
        const float* base = g_tgl + (size_t)b*CC*GSS;
        int o_nn = kh*576 + kw*24;
        int o_fn = hf*576 + kw*24;
        int o_nw = kh*576 + wf*24;
        int o_fw = hf*576 + wf*24;
        float* R = Rs + sj*(64*26);
        for (int i = tid; i < 384; i += 256) {
            int c = i / 6, q = i - c*6;
            const float* pc = base + (size_t)c*GSS + q*4;
            float4 a  = *(const float4*)(pc + o_nn);
            float4 bv = *(const float4*)(pc + o_fn);
            float4 cv = *(const float4*)(pc + o_nw);
            float4 dv = *(const float4*)(pc + o_fw);
            float r0 = 0.75f*(0.75f*a.x + 0.25f*bv.x) + 0.25f*(0.75f*cv.x + 0.25f*dv.x);
            float r1 = 0.75f*(0.75f*a.y + 0.25f*bv.y) + 0.25f*(0.75f*cv.y + 0.25f*dv.y);
            float r2 = 0.75f*(0.75f*a.z + 0.25f*bv.z) + 0.25f*(0.75f*cv.z + 0.25f*dv.z);
            float r3 = 0.75f*(0.75f*a.w + 0.25f*bv.w) + 0.25f*(0.75f*cv.w + 0.25f*dv.w);
            int idx = c*26 + 1 + q*4;
            R[idx+0] = r0; R[idx+1] = r1; R[idx+2] = r2; R[idx+3] = r3;
            if (q == 0) R[c*26]      = r0;   // l-clamp low
            if (q == 5) R[c*26 + 25] = r3;   // l-clamp high
        }
    }
    __syncthreads();

    // ---- stage 2: load A, synthesize G (l-interp), fill tiles --------------
#pragma unroll
    for (int sj = 0; sj < 2; sj++) {
        int st = blockIdx.x*2 + sj;
        int b = st / HWn, hw = st - b*HWn;
        size_t gb = (size_t)b*CC*SS + (size_t)hw*LL;
        float* As = Ab + sj*3328;
        float* Gs = Gb + sj*3328;
        const float* R = Rs + sj*(64*26);
        for (int i = tid; i < 768; i += 256) {
            int c = i / 12, lv = i - c*12;
            size_t off = gb + (size_t)c*SS + lv*4;
            *(float4*)&As[c*52 + lv*4] = *(const float4*)(g_tx + off);
            const float* Rr = R + c*26 + 2*lv;
            float2 r01 = *(const float2*)(Rr);       // R[2lv-1], R[2lv]
            float2 r23 = *(const float2*)(Rr + 2);   // R[2lv+1], R[2lv+2]
            float4 gg;
            gg.x = 0.25f*r01.x + 0.75f*r01.y;
            gg.y = 0.75f*r01.y + 0.25f*r23.x;
            gg.z = 0.25f*r01.y + 0.75f*r23.x;
            gg.w = 0.75f*r23.x + 0.25f*r23.y;
            *(float4*)&Gs[c*52 + lv*4] = gg;
        }
    }
    __syncthreads();

    int sl = tid >> 7;          // site within block
    int s  = tid & 127;         // lane within site group
    const float* As = Ab + sl*3328;
    const float* Gs = Gb + sl*3328;

    // ---- p stats: 2 threads per channel-row, 24 elems each ----
    float pm = 3.402823466e38f;
    {
        int c = s >> 1, hf = s & 1;
        const float* Ar = &As[c*52 + hf*24];
        const float* Gr = &Gs[c*52 + hf*24];
        float ps = 0.f;
#pragma unroll
        for (int q = 0; q < 6; q++) {
            float4 a = *(const float4*)&Ar[q*4];
            float4 g = *(const float4*)&Gr[q*4];
            float t0 = a.x*g.x, t1 = a.y*g.y, t2 = a.z*g.z, t3 = a.w*g.w;
            ps += (t0+t1) + (t2+t3);
            pm = fminf(pm, fminf(fminf(t0,t1), fminf(t2,t3)));
        }
        pp[tid] = ps;
    }
#pragma unroll
    for (int off = 16; off; off >>= 1)
        pm = fminf(pm, __shfl_xor_sync(0xffffffffu, pm, off));
    if ((tid & 31) == 0) pminw[tid >> 5] = pm;

    // ---- raw = A*G^T : 4x8 tile per thread, interleaved mapping ----
    int ti = s >> 3;   // rows i = ti + 16*k, k=0..3
    int tj = s & 7;    // cols j = tj + 8*jj, jj=0..7

    float acc[4][8];
#pragma unroll
    for (int ii = 0; ii < 4; ii++)
#pragma unroll
        for (int jj = 0; jj < 8; jj++) acc[ii][jj] = 0.f;

    for (int l4 = 0; l4 < 12; l4++) {
        float4 av[4];
#pragma unroll
        for (int k = 0; k < 4; k++)
            av[k] = *(const float4*)&As[(ti + 16*k)*52 + l4*4];
#pragma unroll
        for (int jj = 0; jj < 8; jj++) {
            float4 gv = *(const float4*)&Gs[(tj + 8*jj)*52 + l4*4];
#pragma unroll
            for (int k = 0; k < 4; k++) {
                acc[k][jj] = fmaf(av[k].x, gv.x, acc[k][jj]);
                acc[k][jj] = fmaf(av[k].y, gv.y, acc[k][jj]);
                acc[k][jj] = fmaf(av[k].z, gv.z, acc[k][jj]);
                acc[k][jj] = fmaf(av[k].w, gv.w, acc[k][jj]);
            }
        }
    }

    float lmin = acc[0][0], lsum = 0.f;
#pragma unroll
    for (int ii = 0; ii < 4; ii++)
#pragma unroll
        for (int jj = 0; jj < 8; jj++) {
            lmin = fminf(lmin, acc[ii][jj]);
            lsum += acc[ii][jj];
        }
#pragma unroll
    for (int off = 16; off; off >>= 1) {
        lmin = fminf(lmin, __shfl_xor_sync(0xffffffffu, lmin, off));
        lsum += __shfl_xor_sync(0xffffffffu, lsum, off);
    }
    int wid = tid >> 5, lane = tid & 31;
    if (!lane) { rmin[wid] = lmin; rsum[wid] = lsum; }
    __syncthreads();

    // per-(b,c) p sums, transposed layout [bc][hw] for coalesced reduce
    if (s < 64) {
        int st = blockIdx.x*2 + sl;
        int b = st / HWn, hw = st - b*HWn;
        g_sitechan[(size_t)(b*64 + s)*HWn + hw] =
            pp[sl*128 + 2*s] + pp[sl*128 + 2*s + 1];
    }

    if (s == 0)   // tid 0 (site 0) and tid 128 (site 1)
        g_sitesum[blockIdx.x*2 + sl] =
            (rsum[sl*4+0] + rsum[sl*4+1]) + (rsum[sl*4+2] + rsum[sl*4+3]);

    if (tid == 0) {
        float m = fminf(fminf(fminf(rmin[0], rmin[1]), fminf(rmin[2], rmin[3])),
                        fminf(fminf(rmin[4], rmin[5]), fminf(rmin[6], rmin[7])));
        atomicMin(&g_min_d_key, fkey(m));
        float pmn = fminf(fminf(fminf(pminw[0], pminw[1]), fminf(pminw[2], pminw[3])),
                          fminf(fminf(pminw[4], pminw[5]), fminf(pminw[6], pminw[7])));
        atomicMin(&g_min_p_key, fkey(pmn));
    }
}

// ------- merged reductions: blocks 0..127 = per-(b,c) p; 128..129 = d -------
__global__ void k_reduce_all() {
    __shared__ float sh[256];
    int tid = threadIdx.x;
    if (blockIdx.x < 128) {
        int bc = blockIdx.x;
        const float* row = g_sitechan + (size_t)bc * HWn;
        float s = 0.f;
        for (int i = tid; i < HWn; i += 256)   // coalesced
            s += row[i];
        sh[tid] = s;
        __syncthreads();
        for (int st = 128; st > 0; st >>= 1) {
            if (tid < st) sh[tid] += sh[tid + st];
            __syncthreads();
        }
        if (tid == 0) {
            float m1 = funkey(g_min_p_key);
            g_inv1[bc] = 1.0f / (sh[0] - m1 * (float)SS);
        }
    } else {
        int b = blockIdx.x - 128;
        float s = 0.f;
        for (int i = tid; i < HWn; i += 256) s += g_sitesum[b * HWn + i];
        sh[tid] = s;
        __syncthreads();
        for (int st = 128; st > 0; st >>= 1) {
            if (tid < st) sh[tid] += sh[tid + st];
            __syncthreads();
        }
        if (tid == 0) {
            float m2 = funkey(g_min_d_key);
            g_inv2[b] = 1.0f / (sh[0] - m2 * 9437184.0f);
        }
    }
}

// -------- d (+ fused p): D = (G*(A^T X) - m2*colsum(X))*inv2 ----------------
// R7/R11-exact compute shape; G re-synthesized from L2-resident g_tgl in two
// channel halves (R buffer 32x26) -> smem 43.2KB keeps occ 5.
#define KD_SMEM ((3328 + 3328 + 3264 + 32*26 + 48)*4)
__global__ __launch_bounds__(128, 5) void k_d(const float* __restrict__ x,
                                              float* __restrict__ outp,
                                              float* __restrict__ outd) {
    extern __shared__ float dyn[];
    float* As = dyn;            // 64*52   (phase1 input; becomes Ms)
    float* Ms = dyn;            // 48*52   overlay
    float* Xs = As + 3328;      // 64*52
    float* Gt = Xs + 3328;      // 48*68 (transposed, swizzled)
    float* Rh = Gt + 3264;      // 32*26  (half-channel interp rows)
    float* cs = Rh + 832;       // 48
    int tid = threadIdx.x;
    int site = blockIdx.x;
    int b = site / HWn, hw = site - b*HWn;
    size_t gb = (size_t)b*CC*SS + (size_t)hw*LL;

    // tap geometry (same as stats stage 1)
    int h = hw / 48, w = hw - h*48;
    int kh = h >> 1, kw = w >> 1;
    int hf = (h & 1) ? (kh+1 > 23 ? 23 : kh+1) : (kh-1 < 0 ? 0 : kh-1);
    int wf = (w & 1) ? (kw+1 > 23 ? 23 : kw+1) : (kw-1 < 0 ? 0 : kw-1);
    const float* base = g_tgl + (size_t)b*CC*GSS;
    int o_nn = kh*576 + kw*24;
    int o_fn = hf*576 + kw*24;
    int o_nw = kh*576 + wf*24;
    int o_fw = hf*576 + wf*24;

    float m1 = funkey(g_min_p_key);
#pragma unroll
    for (int half = 0; half < 2; half++) {
        int c0 = half * 32;
        // stage R for channels c0..c0+31 (bit-identical to stats arith)
        for (int i = tid; i < 192; i += 128) {
            int cl = i / 6, q = i - cl*6;
            const float* pc = base + (size_t)(c0 + cl)*GSS + q*4;
            float4 a  = *(const float4*)(pc + o_nn);
            float4 bv = *(const float4*)(pc + o_fn);
            float4 cv = *(const float4*)(pc + o_nw);
            float4 dv = *(const float4*)(pc + o_fw);
            float r0 = 0.75f*(0.75f*a.x + 0.25f*bv.x) + 0.25f*(0.75f*cv.x + 0.25f*dv.x);
            float r1 = 0.75f*(0.75f*a.y + 0.25f*bv.y) + 0.25f*(0.75f*cv.y + 0.25f*dv.y);
            float r2 = 0.75f*(0.75f*a.z + 0.25f*bv.z) + 0.25f*(0.75f*cv.z + 0.25f*dv.z);
            float r3 = 0.75f*(0.75f*a.w + 0.25f*bv.w) + 0.25f*(0.75f*cv.w + 0.25f*dv.w);
            int idx = cl*26 + 1 + q*4;
            Rh[idx+0] = r0; Rh[idx+1] = r1; Rh[idx+2] = r2; Rh[idx+3] = r3;
            if (q == 0) Rh[cl*26]      = r0;
            if (q == 5) Rh[cl*26 + 25] = r3;
        }
        __syncthreads();

        for (int i = tid; i < 384; i += 128) {
            int cl = i / 12, lv = i - cl*12;
            int c = c0 + cl;
            size_t off = gb + (size_t)c*SS + lv*4;
            float4 a  = __ldcs((const float4*)(g_tx + off));
            float4 xv = __ldcs((const float4*)(x + off));
            const float* Rr = Rh + cl*26 + 2*lv;
            float2 r01 = *(const float2*)(Rr);
            float2 r23 = *(const float2*)(Rr + 2);
            float4 gg;
            gg.x = 0.25f*r01.x + 0.75f*r01.y;
            gg.y = 0.75f*r01.y + 0.25f*r23.x;
            gg.z = 0.25f*r01.y + 0.75f*r23.x;
            gg.w = 0.75f*r23.x + 0.25f*r23.y;
            *(float4*)&As[c*52 + lv*4] = a;
            *(float4*)&Xs[c*52 + lv*4] = xv;
            {
                float gv[4] = {gg.x, gg.y, gg.z, gg.w};
#pragma unroll
                for (int q = 0; q < 4; q++) {
                    int row = lv*4 + q;
                    int colp = c ^ (8 * ((row >> 3) & 3));
                    Gt[row*68 + colp] = gv[q];
                }
            }
            float inv1 = g_inv1[b*64 + c];
            float4 o;
            o.x = (a.x*gg.x - m1) * xv.x * inv1;
            o.y = (a.y*gg.y - m1) * xv.y * inv1;
            o.z = (a.z*gg.z - m1) * xv.z * inv1;
            o.w = (a.w*gg.w - m1) * xv.w * inv1;
            __stcs((float4*)(outp + off), o);
        }
        __syncthreads();   // Rh reuse barrier (also finalizes tiles on half 1)
    }

    if (tid < 48) {
        float s = 0.f;
#pragma unroll 8
        for (int c = 0; c < 64; c++) s += Xs[c*52 + tid];
        cs[tid] = s;
    }

    // phase 1: M[lp][l] = sum_c A[c][lp] * X[c][l] (accumulate in registers)
    float p1acc[3][6];
    int p1ti = tid >> 3;
    int p1tj = tid & 7;
    {
#pragma unroll
        for (int ii = 0; ii < 3; ii++)
#pragma unroll
            for (int jj = 0; jj < 6; jj++) p1acc[ii][jj] = 0.f;

#pragma unroll 4
        for (int c = 0; c < 64; c++) {
            float a0 = As[c*52 + p1ti*3 + 0];
            float a1 = As[c*52 + p1ti*3 + 1];
            float a2 = As[c*52 + p1ti*3 + 2];
            float xv[6];
#pragma unroll
            for (int jj = 0; jj < 6; jj++) xv[jj] = Xs[c*52 + p1tj*6 + jj];
#pragma unroll
            for (int jj = 0; jj < 6; jj++) {
                p1acc[0][jj] = fmaf(a0, xv[jj], p1acc[0][jj]);
                p1acc[1][jj] = fmaf(a1, xv[jj], p1acc[1][jj]);
                p1acc[2][jj] = fmaf(a2, xv[jj], p1acc[2][jj]);
            }
        }
    }
    __syncthreads();   // all As reads done -> safe to overlay Ms

#pragma unroll
    for (int ii = 0; ii < 3; ii++)
#pragma unroll
        for (int jj = 0; jj < 6; jj++)
            Ms[(p1ti*3+ii)*52 + p1tj*6 + jj] = p1acc[ii][jj];
    __syncthreads();

    // phase 2: D[j][l] = sum_lp Gt[lp][j] * M[lp][l]
    float m2  = funkey(g_min_d_key);
    float inv = g_inv2[b];
    {
        int ti = tid >> 4;
        int tj = tid & 15;
        float acc[8][3];
#pragma unroll
        for (int k = 0; k < 8; k++)
#pragma unroll
            for (int m = 0; m < 3; m++) acc[k][m] = 0.f;

#pragma unroll 4
        for (int lp = 0; lp < 48; lp++) {
            int jbase = (ti*8) ^ (8 * ((lp >> 3) & 3));
            float4 gA = *(const float4*)&Gt[lp*68 + jbase];
            float4 gB = *(const float4*)&Gt[lp*68 + jbase + 4];
            float gk[8] = {gA.x,gA.y,gA.z,gA.w,gB.x,gB.y,gB.z,gB.w};
            float q0 = Ms[lp*52 + tj*3 + 0];
            float q1 = Ms[lp*52 + tj*3 + 1];
            float q2 = Ms[lp*52 + tj*3 + 2];
#pragma unroll
            for (int k = 0; k < 8; k++) {
                acc[k][0] = fmaf(gk[k], q0, acc[k][0]);
                acc[k][1] = fmaf(gk[k], q1, acc[k][1]);
                acc[k][2] = fmaf(gk[k], q2, acc[k][2]);
            }
        }

        float cc0 = cs[tj*3+0], cc1 = cs[tj*3+1], cc2 = cs[tj*3+2];
#pragma unroll
        for (int k = 0; k < 8; k++) {
            int j = ti*8 + k;
            size_t ob = gb + (size_t)j*SS + tj*3;
            __stcs(outd + ob + 0, (acc[k][0] - m2*cc0) * inv);
            __stcs(outd + ob + 1, (acc[k][1] - m2*cc1) * inv);
            __stcs(outd + ob + 2, (acc[k][2] - m2*cc2) * inv);
        }
    }
}

// ---------------- launch ----------------------------------------------------
extern "C" void kernel_launch(void* const* d_in, const int* in_sizes, int n_in,
                              void* d_out, int out_size) {
    const float* x  = (const float*)d_in[0];
    const float* g  = (const float*)d_in[1];
    const float* W1 = (const float*)d_in[2];
    const float* b1 = (const float*)d_in[3];
    const float* W2 = (const float*)d_in[4];
    const float* b2 = (const float*)d_in[5];

    float* out  = (float*)d_out;
    float* outp = out;
    float* outd = out + (size_t)TOTAL;

    cudaFuncSetAttribute(k_chanmix, cudaFuncAttributeMaxDynamicSharedMemorySize, CM_SMEM);
    cudaFuncSetAttribute(k_stats_d, cudaFuncAttributeMaxDynamicSharedMemorySize, SD_SMEM);
    cudaFuncSetAttribute(k_d,       cudaFuncAttributeMaxDynamicSharedMemorySize, KD_SMEM);

    { dim3 gg(GSS/128, BB); k_chanmix<<<gg, 128, CM_SMEM>>>(g, W2, b2, 1, GSS); }
    { dim3 gx(SS/128,  BB); k_chanmix<<<gx, 128, CM_SMEM>>>(x, W1, b1, 0, SS); }

    k_stats_d<<<NSITES/2, 256, SD_SMEM>>>();
    k_reduce_all<<<130, 256>>>();

    k_d<<<NSITES, 128, KD_SMEM>>>(x, outp, outd);
}

// round 16
// speedup vs baseline: 1.0803x; 1.0103x over previous
#include <cuda_runtime.h>

#define BB 2
#define CC 64
#define HH 48
#define WWn 48
#define LL 48
#define HWn (HH*WWn)            // 2304
#define SS (HH*WWn*LL)          // 110592
#define GHn 24
#define GSS (GHn*GHn*GHn)       // 13824
#define NSITES (BB*HWn)         // 4608
#define TOTAL (BB*CC*SS)        // 14155776

// ---------------- scratch ----------------
__device__ float g_tx[TOTAL];
__device__ float g_tgl[BB*CC*GSS];
__device__ unsigned g_min_p_key;
__device__ unsigned g_min_d_key;
__device__ float g_sitechan[BB*CC*HWn];   // [bc][site-hw] transposed layout
__device__ float g_sitesum[NSITES];
__device__ float g_inv1[BB*CC];
__device__ float g_inv2[BB];

__device__ __forceinline__ unsigned fkey(float f) {
    unsigned u = __float_as_uint(f);
    return (u & 0x80000000u) ? ~u : (u | 0x80000000u);
}
__device__ __forceinline__ float funkey(unsigned k) {
    unsigned u = (k & 0x80000000u) ? (k ^ 0x80000000u) : ~k;
    return __uint_as_float(u);
}

// ---------------- channel-mix GEMM: 128 sites x 64 outs per block ----------
#define CM_SMEM ((64*68 + 64 + 64*132)*4)
__global__ __launch_bounds__(128, 4) void k_chanmix(
        const float* __restrict__ in, const float* __restrict__ Wm,
        const float* __restrict__ bias, int which, int Ssz) {
    extern __shared__ float dyn[];
    float* Wt  = dyn;             // 64*68
    float* bsm = Wt + 64*68;      // 64
    float* Xs  = bsm + 64;        // 64*132
    int tid = threadIdx.x;

    // fold the min-key init into the first kernel (g-side, block (0,0))
    if (which && blockIdx.x == 0 && blockIdx.y == 0 && tid == 0) {
        g_min_p_key = 0xFFFFFFFFu;
        g_min_d_key = 0xFFFFFFFFu;
    }

    for (int i = tid; i < 4096; i += 128) {
        int o = i >> 6, c = i & 63;
        Wt[c*68 + o] = Wm[i];
    }
    if (tid < 64) bsm[tid] = bias[tid];

    int b = blockIdx.y;
    size_t sbase = (size_t)b * CC * Ssz + (size_t)blockIdx.x * 128;
    const float* src = in + sbase;
    for (int i = tid; i < 64*32; i += 128) {
        int c = i >> 5, sv = i & 31;
        float4 v = *(const float4*)(src + (size_t)c*Ssz + sv*4);
        *(float4*)&Xs[c*132 + sv*4] = v;
    }
    __syncthreads();

    int og = tid & 3;
    int sg = tid >> 2;
    float acc[16][4];
#pragma unroll
    for (int j = 0; j < 16; j++) {
        float bv = bsm[og*16 + j];
        acc[j][0]=bv; acc[j][1]=bv; acc[j][2]=bv; acc[j][3]=bv;
    }

#pragma unroll 4
    for (int c = 0; c < 64; c++) {
        float4 xv = *(const float4*)&Xs[c*132 + sg*4];
        float xk[4] = {xv.x, xv.y, xv.z, xv.w};
#pragma unroll
        for (int q = 0; q < 4; q++) {
            float4 wv = *(const float4*)&Wt[c*68 + og*16 + q*4];
            float wk[4] = {wv.x, wv.y, wv.z, wv.w};
#pragma unroll
            for (int jj = 0; jj < 4; jj++)
#pragma unroll
                for (int kk = 0; kk < 4; kk++)
                    acc[q*4+jj][kk] = fmaf(wk[jj], xk[kk], acc[q*4+jj][kk]);
        }
    }

    float* outp = (which ? (float*)g_tgl : (float*)g_tx) + sbase;
#pragma unroll
    for (int j = 0; j < 16; j++) {
        int o = og*16 + j;
        float4 v = make_float4(acc[j][0], acc[j][1], acc[j][2], acc[j][3]);
        *(float4*)(outp + (size_t)o*Ssz + sg*4) = v;
    }
}

// ---- stats + fused trilinear upsample (R staged in-place in G tiles) -------
// smem: As/Gs [2][64*52] only -> 53.2KB -> 4 blocks/SM (32 warps).
#define SD_SMEM (4*3328*4)
__global__ __launch_bounds__(256, 4) void k_stats_d() {
    extern __shared__ float dyn[];
    float* Ab = dyn;                 // [2][3328]
    float* Gb = dyn + 2*3328;        // [2][3328]  (R rows staged at [c*52+0..25])
    __shared__ float pp[256];
    __shared__ float rmin[8], rsum[8], pminw[8];
    int tid = threadIdx.x;

    // ---- stage 1: load A tiles; compute hw-interp rows R into G tiles ------
#pragma unroll
    for (int sj = 0; sj < 2; sj++) {
        int st = blockIdx.x*2 + sj;
        int b = st / HWn, hw = st - b*HWn;
        int h = hw / 48, w = hw - h*48;
        int kh = h >> 1, kw = w >> 1;
        int hf = (h & 1) ? (kh+1 > 23 ? 23 : kh+1) : (kh-1 < 0 ? 0 : kh-1);
        int wf = (w & 1) ? (kw+1 > 23 ? 23 : kw+1) : (kw-1 < 0 ? 0 : kw-1);
        const float* base = g_tgl + (size_t)b*CC*GSS;
        int o_nn = kh*576 + kw*24;
        int o_fn = hf*576 + kw*24;
        int o_nw = kh*576 + wf*24;
        int o_fw = hf*576 + wf*24;
        size_t gb = (size_t)b*CC*SS + (size_t)hw*LL;
        float* As = Ab + sj*3328;
        float* R  = Gb + sj*3328;       // R rows live at [c*52 + 0..25]

        for (int i = tid; i < 768; i += 256) {
            int c = i / 12, lv = i - c*12;
            size_t off = gb + (size_t)c*SS + lv*4;
            *(float4*)&As[c*52 + lv*4] = *(const float4*)(g_tx + off);
        }
        for (int i = tid; i < 384; i += 256) {
            int c = i / 6, q = i - c*6;
            const float* pc = base + (size_t)c*GSS + q*4;
            float4 a  = *(const float4*)(pc + o_nn);
            float4 bv = *(const float4*)(pc + o_fn);
            float4 cv = *(const float4*)(pc + o_nw);
            float4 dv = *(const float4*)(pc + o_fw);
            float r0 = 0.75f*(0.75f*a.x + 0.25f*bv.x) + 0.25f*(0.75f*cv.x + 0.25f*dv.x);
            float r1 = 0.75f*(0.75f*a.y + 0.25f*bv.y) + 0.25f*(0.75f*cv.y + 0.25f*dv.y);
            float r2 = 0.75f*(0.75f*a.z + 0.25f*bv.z) + 0.25f*(0.75f*cv.z + 0.25f*dv.z);
            float r3 = 0.75f*(0.75f*a.w + 0.25f*bv.w) + 0.25f*(0.75f*cv.w + 0.25f*dv.w);
            int idx = c*52 + 1 + q*4;
            R[idx+0] = r0; R[idx+1] = r1; R[idx+2] = r2; R[idx+3] = r3;
            if (q == 0) R[c*52]      = r0;   // l-clamp low
            if (q == 5) R[c*52 + 25] = r3;   // l-clamp high
        }
    }
    __syncthreads();

    // ---- stage 2: in-place expand R -> G (register staging, 2 thr/row) ----
    {
        int row = tid >> 1;              // 0..127 : (site, channel)
        int sl2 = row >> 6, c = row & 63;
        int hf = tid & 1;                // l-half: outputs hf*24 .. +23
        float* Gr = Gb + sl2*3328 + c*52;
        float r[14];
#pragma unroll
        for (int t = 0; t < 14; t++) r[t] = Gr[hf*12 + t];
        __syncthreads();                 // all R reads before any G writes
#pragma unroll
        for (int k = 0; k < 12; k++) {
            Gr[hf*24 + 2*k]     = 0.25f*r[k]   + 0.75f*r[k+1];
            Gr[hf*24 + 2*k + 1] = 0.75f*r[k+1] + 0.25f*r[k+2];
        }
    }
    __syncthreads();

    int sl = tid >> 7;          // site within block
    int s  = tid & 127;         // lane within site group
    const float* As = Ab + sl*3328;
    const float* Gs = Gb + sl*3328;

    // ---- p stats: 2 threads per channel-row, 24 elems each ----
    float pm = 3.402823466e38f;
    {
        int c = s >> 1, hf = s & 1;
        const float* Ar = &As[c*52 + hf*24];
        const float* Gr = &Gs[c*52 + hf*24];
        float ps = 0.f;
#pragma unroll
        for (int q = 0; q < 6; q++) {
            float4 a = *(const float4*)&Ar[q*4];
            float4 g = *(const float4*)&Gr[q*4];
            float t0 = a.x*g.x, t1 = a.y*g.y, t2 = a.z*g.z, t3 = a.w*g.w;
            ps += (t0+t1) + (t2+t3);
            pm = fminf(pm, fminf(fminf(t0,t1), fminf(t2,t3)));
        }
        pp[tid] = ps;
    }
#pragma unroll
    for (int off = 16; off; off >>= 1)
        pm = fminf(pm, __shfl_xor_sync(0xffffffffu, pm, off));
    if ((tid & 31) == 0) pminw[tid >> 5] = pm;

    // ---- raw = A*G^T : 4x8 tile per thread, interleaved mapping ----
    int ti = s >> 3;   // rows i = ti + 16*k, k=0..3
    int tj = s & 7;    // cols j = tj + 8*jj, jj=0..7

    float acc[4][8];
#pragma unroll
    for (int ii = 0; ii < 4; ii++)
#pragma unroll
        for (int jj = 0; jj < 8; jj++) acc[ii][jj] = 0.f;

    for (int l4 = 0; l4 < 12; l4++) {
        float4 av[4];
#pragma unroll
        for (int k = 0; k < 4; k++)
            av[k] = *(const float4*)&As[(ti + 16*k)*52 + l4*4];
#pragma unroll
        for (int jj = 0; jj < 8; jj++) {
            float4 gv = *(const float4*)&Gs[(tj + 8*jj)*52 + l4*4];
#pragma unroll
            for (int k = 0; k < 4; k++) {
                acc[k][jj] = fmaf(av[k].x, gv.x, acc[k][jj]);
                acc[k][jj] = fmaf(av[k].y, gv.y, acc[k][jj]);
                acc[k][jj] = fmaf(av[k].z, gv.z, acc[k][jj]);
                acc[k][jj] = fmaf(av[k].w, gv.w, acc[k][jj]);
            }
        }
    }

    float lmin = acc[0][0], lsum = 0.f;
#pragma unroll
    for (int ii = 0; ii < 4; ii++)
#pragma unroll
        for (int jj = 0; jj < 8; jj++) {
            lmin = fminf(lmin, acc[ii][jj]);
            lsum += acc[ii][jj];
        }
#pragma unroll
    for (int off = 16; off; off >>= 1) {
        lmin = fminf(lmin, __shfl_xor_sync(0xffffffffu, lmin, off));
        lsum += __shfl_xor_sync(0xffffffffu, lsum, off);
    }
    int wid = tid >> 5, lane = tid & 31;
    if (!lane) { rmin[wid] = lmin; rsum[wid] = lsum; }
    __syncthreads();

    // per-(b,c) p sums, transposed layout [bc][hw] for coalesced reduce
    if (s < 64) {
        int st = blockIdx.x*2 + sl;
        int b = st / HWn, hw = st - b*HWn;
        g_sitechan[(size_t)(b*64 + s)*HWn + hw] =
            pp[sl*128 + 2*s] + pp[sl*128 + 2*s + 1];
    }

    if (s == 0)   // tid 0 (site 0) and tid 128 (site 1)
        g_sitesum[blockIdx.x*2 + sl] =
            (rsum[sl*4+0] + rsum[sl*4+1]) + (rsum[sl*4+2] + rsum[sl*4+3]);

    if (tid == 0) {
        float m = fminf(fminf(fminf(rmin[0], rmin[1]), fminf(rmin[2], rmin[3])),
                        fminf(fminf(rmin[4], rmin[5]), fminf(rmin[6], rmin[7])));
        atomicMin(&g_min_d_key, fkey(m));
        float pmn = fminf(fminf(fminf(pminw[0], pminw[1]), fminf(pminw[2], pminw[3])),
                          fminf(fminf(pminw[4], pminw[5]), fminf(pminw[6], pminw[7])));
        atomicMin(&g_min_p_key, fkey(pmn));
    }
}

// ------- merged reductions: blocks 0..127 = per-(b,c) p; 128..129 = d -------
__global__ void k_reduce_all() {
    __shared__ float sh[256];
    int tid = threadIdx.x;
    if (blockIdx.x < 128) {
        int bc = blockIdx.x;
        const float* row = g_sitechan + (size_t)bc * HWn;
        float s = 0.f;
        for (int i = tid; i < HWn; i += 256)   // coalesced
            s += row[i];
        sh[tid] = s;
        __syncthreads();
        for (int st = 128; st > 0; st >>= 1) {
            if (tid < st) sh[tid] += sh[tid + st];
            __syncthreads();
        }
        if (tid == 0) {
            float m1 = funkey(g_min_p_key);
            g_inv1[bc] = 1.0f / (sh[0] - m1 * (float)SS);
        }
    } else {
        int b = blockIdx.x - 128;
        float s = 0.f;
        for (int i = tid; i < HWn; i += 256) s += g_sitesum[b * HWn + i];
        sh[tid] = s;
        __syncthreads();
        for (int st = 128; st > 0; st >>= 1) {
            if (tid < st) sh[tid] += sh[tid + st];
            __syncthreads();
        }
        if (tid == 0) {
            float m2 = funkey(g_min_d_key);
            g_inv2[b] = 1.0f / (sh[0] - m2 * 9437184.0f);
        }
    }
}

// -------- d (+ fused p): D = (G*(A^T X) - m2*colsum(X))*inv2 ----------------
// R15-exact: G re-synthesized from L2-resident g_tgl in two channel halves.
#define KD_SMEM ((3328 + 3328 + 3264 + 32*26 + 48)*4)
__global__ __launch_bounds__(128, 5) void k_d(const float* __restrict__ x,
                                              float* __restrict__ outp,
                                              float* __restrict__ outd) {
    extern __shared__ float dyn[];
    float* As = dyn;            // 64*52   (phase1 input; becomes Ms)
    float* Ms = dyn;            // 48*52   overlay
    float* Xs = As + 3328;      // 64*52
    float* Gt = Xs + 3328;      // 48*68 (transposed, swizzled)
    float* Rh = Gt + 3264;      // 32*26  (half-channel interp rows)
    float* cs = Rh + 832;       // 48
    int tid = threadIdx.x;
    int site = blockIdx.x;
    int b = site / HWn, hw = site - b*HWn;
    size_t gb = (size_t)b*CC*SS + (size_t)hw*LL;

    // tap geometry (same as stats stage 1)
    int h = hw / 48, w = hw - h*48;
    int kh = h >> 1, kw = w >> 1;
    int hf = (h & 1) ? (kh+1 > 23 ? 23 : kh+1) : (kh-1 < 0 ? 0 : kh-1);
    int wf = (w & 1) ? (kw+1 > 23 ? 23 : kw+1) : (kw-1 < 0 ? 0 : kw-1);
    const float* base = g_tgl + (size_t)b*CC*GSS;
    int o_nn = kh*576 + kw*24;
    int o_fn = hf*576 + kw*24;
    int o_nw = kh*576 + wf*24;
    int o_fw = hf*576 + wf*24;

    float m1 = funkey(g_min_p_key);
#pragma unroll
    for (int half = 0; half < 2; half++) {
        int c0 = half * 32;
        // stage R for channels c0..c0+31 (bit-identical to stats arith)
        for (int i = tid; i < 192; i += 128) {
            int cl = i / 6, q = i - cl*6;
            const float* pc = base + (size_t)(c0 + cl)*GSS + q*4;
            float4 a  = *(const float4*)(pc + o_nn);
            float4 bv = *(const float4*)(pc + o_fn);
            float4 cv = *(const float4*)(pc + o_nw);
            float4 dv = *(const float4*)(pc + o_fw);
            float r0 = 0.75f*(0.75f*a.x + 0.25f*bv.x) + 0.25f*(0.75f*cv.x + 0.25f*dv.x);
            float r1 = 0.75f*(0.75f*a.y + 0.25f*bv.y) + 0.25f*(0.75f*cv.y + 0.25f*dv.y);
            float r2 = 0.75f*(0.75f*a.z + 0.25f*bv.z) + 0.25f*(0.75f*cv.z + 0.25f*dv.z);
            float r3 = 0.75f*(0.75f*a.w + 0.25f*bv.w) + 0.25f*(0.75f*cv.w + 0.25f*dv.w);
            int idx = cl*26 + 1 + q*4;
            Rh[idx+0] = r0; Rh[idx+1] = r1; Rh[idx+2] = r2; Rh[idx+3] = r3;
            if (q == 0) Rh[cl*26]      = r0;
            if (q == 5) Rh[cl*26 + 25] = r3;
        }
        __syncthreads();

        for (int i = tid; i < 384; i += 128) {
            int cl = i / 12, lv = i - cl*12;
            int c = c0 + cl;
            size_t off = gb + (size_t)c*SS + lv*4;
            float4 a  = __ldcs((const float4*)(g_tx + off));
            float4 xv = __ldcs((const float4*)(x + off));
            const float* Rr = Rh + cl*26 + 2*lv;
            float2 r01 = *(const float2*)(Rr);
            float2 r23 = *(const float2*)(Rr + 2);
            float4 gg;
            gg.x = 0.25f*r01.x + 0.75f*r01.y;
            gg.y = 0.75f*r01.y + 0.25f*r23.x;
            gg.z = 0.25f*r01.y + 0.75f*r23.x;
            gg.w = 0.75f*r23.x + 0.25f*r23.y;
            *(float4*)&As[c*52 + lv*4] = a;
            *(float4*)&Xs[c*52 + lv*4] = xv;
            {
                float gv[4] = {gg.x, gg.y, gg.z, gg.w};
#pragma unroll
                for (int q = 0; q < 4; q++) {
                    int row = lv*4 + q;
                    int colp = c ^ (8 * ((row >> 3) & 3));
                    Gt[row*68 + colp] = gv[q];
                }
            }
            float inv1 = g_inv1[b*64 + c];
            float4 o;
            o.x = (a.x*gg.x - m1) * xv.x * inv1;
            o.y = (a.y*gg.y - m1) * xv.y * inv1;
            o.z = (a.z*gg.z - m1) * xv.z * inv1;
            o.w = (a.w*gg.w - m1) * xv.w * inv1;
            __stcs((float4*)(outp + off), o);
        }
        __syncthreads();   // Rh reuse barrier (also finalizes tiles on half 1)
    }

    if (tid < 48) {
        float s = 0.f;
#pragma unroll 8
        for (int c = 0; c < 64; c++) s += Xs[c*52 + tid];
        cs[tid] = s;
    }

    // phase 1: M[lp][l] = sum_c A[c][lp] * X[c][l] (accumulate in registers)
    float p1acc[3][6];
    int p1ti = tid >> 3;
    int p1tj = tid & 7;
    {
#pragma unroll
        for (int ii = 0; ii < 3; ii++)
#pragma unroll
            for (int jj = 0; jj < 6; jj++) p1acc[ii][jj] = 0.f;

#pragma unroll 4
        for (int c = 0; c < 64; c++) {
            float a0 = As[c*52 + p1ti*3 + 0];
            float a1 = As[c*52 + p1ti*3 + 1];
            float a2 = As[c*52 + p1ti*3 + 2];
            float xv[6];
#pragma unroll
            for (int jj = 0; jj < 6; jj++) xv[jj] = Xs[c*52 + p1tj*6 + jj];
#pragma unroll
            for (int jj = 0; jj < 6; jj++) {
                p1acc[0][jj] = fmaf(a0, xv[jj], p1acc[0][jj]);
                p1acc[1][jj] = fmaf(a1, xv[jj], p1acc[1][jj]);
                p1acc[2][jj] = fmaf(a2, xv[jj], p1acc[2][jj]);
            }
        }
    }
    __syncthreads();   // all As reads done -> safe to overlay Ms

#pragma unroll
    for (int ii = 0; ii < 3; ii++)
#pragma unroll
        for (int jj = 0; jj < 6; jj++)
            Ms[(p1ti*3+ii)*52 + p1tj*6 + jj] = p1acc[ii][jj];
    __syncthreads();

    // phase 2: D[j][l] = sum_lp Gt[lp][j] * M[lp][l]
    float m2  = funkey(g_min_d_key);
    float inv = g_inv2[b];
    {
        int ti = tid >> 4;
        int tj = tid & 15;
        float acc[8][3];
#pragma unroll
        for (int k = 0; k < 8; k++)
#pragma unroll
            for (int m = 0; m < 3; m++) acc[k][m] = 0.f;

#pragma unroll 4
        for (int lp = 0; lp < 48; lp++) {
            int jbase = (ti*8) ^ (8 * ((lp >> 3) & 3));
            float4 gA = *(const float4*)&Gt[lp*68 + jbase];
            float4 gB = *(const float4*)&Gt[lp*68 + jbase + 4];
            float gk[8] = {gA.x,gA.y,gA.z,gA.w,gB.x,gB.y,gB.z,gB.w};
            float q0 = Ms[lp*52 + tj*3 + 0];
            float q1 = Ms[lp*52 + tj*3 + 1];
            float q2 = Ms[lp*52 + tj*3 + 2];
#pragma unroll
            for (int k = 0; k < 8; k++) {
                acc[k][0] = fmaf(gk[k], q0, acc[k][0]);
                acc[k][1] = fmaf(gk[k], q1, acc[k][1]);
                acc[k][2] = fmaf(gk[k], q2, acc[k][2]);
            }
        }

        float cc0 = cs[tj*3+0], cc1 = cs[tj*3+1], cc2 = cs[tj*3+2];
#pragma unroll
        for (int k = 0; k < 8; k++) {
            int j = ti*8 + k;
            size_t ob = gb + (size_t)j*SS + tj*3;
            __stcs(outd + ob + 0, (acc[k][0] - m2*cc0) * inv);
            __stcs(outd + ob + 1, (acc[k][1] - m2*cc1) * inv);
            __stcs(outd + ob + 2, (acc[k][2] - m2*cc2) * inv);
        }
    }
}

// ---------------- launch ----------------------------------------------------
extern "C" void kernel_launch(void* const* d_in, const int* in_sizes, int n_in,
                              void* d_out, int out_size) {
    const float* x  = (const float*)d_in[0];
    const float* g  = (const float*)d_in[1];
    const float* W1 = (const float*)d_in[2];
    const float* b1 = (const float*)d_in[3];
    const float* W2 = (const float*)d_in[4];
    const float* b2 = (const float*)d_in[5];

    float* out  = (float*)d_out;
    float* outp = out;
    float* outd = out + (size_t)TOTAL;

    cudaFuncSetAttribute(k_chanmix, cudaFuncAttributeMaxDynamicSharedMemorySize, CM_SMEM);
    cudaFuncSetAttribute(k_stats_d, cudaFuncAttributeMaxDynamicSharedMemorySize, SD_SMEM);
    cudaFuncSetAttribute(k_d,       cudaFuncAttributeMaxDynamicSharedMemorySize, KD_SMEM);

    { dim3 gg(GSS/128, BB); k_chanmix<<<gg, 128, CM_SMEM>>>(g, W2, b2, 1, GSS); }
    { dim3 gx(SS/128,  BB); k_chanmix<<<gx, 128, CM_SMEM>>>(x, W1, b1, 0, SS); }

    k_stats_d<<<NSITES/2, 256, SD_SMEM>>>();
    k_reduce_all<<<130, 256>>>();

    k_d<<<NSITES, 128, KD_SMEM>>>(x, outp, outd);
}

// round 17
// speedup vs baseline: 1.1040x; 1.0219x over previous
#include <cuda_runtime.h>

#define BB 2
#define CC 64
#define HH 48
#define WWn 48
#define LL 48
#define HWn (HH*WWn)            // 2304
#define SS (HH*WWn*LL)          // 110592
#define GHn 24
#define GSS (GHn*GHn*GHn)       // 13824
#define NSITES (BB*HWn)         // 4608
#define TOTAL (BB*CC*SS)        // 14155776
#define XBLK (SS/128)           // 864

// ---------------- scratch ----------------
__device__ float g_tx[TOTAL];
__device__ float g_tgl[BB*CC*GSS];
__device__ unsigned g_min_p_key;
__device__ unsigned g_min_d_key;
__device__ float g_sitechan[BB*CC*HWn];   // [bc][site-hw] transposed layout
__device__ float g_sitesum[NSITES];
__device__ float g_inv1[BB*CC];
__device__ float g_inv2[BB];

__device__ __forceinline__ unsigned fkey(float f) {
    unsigned u = __float_as_uint(f);
    return (u & 0x80000000u) ? ~u : (u | 0x80000000u);
}
__device__ __forceinline__ float funkey(unsigned k) {
    unsigned u = (k & 0x80000000u) ? (k ^ 0x80000000u) : ~k;
    return __uint_as_float(u);
}

// ------- merged channel-mix GEMM: x-side blocks [0,864), g-side [864,972) ---
#define CM_SMEM ((64*68 + 64 + 64*132)*4)
__global__ __launch_bounds__(128, 4) void k_chanmix(
        const float* __restrict__ xin, const float* __restrict__ W1,
        const float* __restrict__ b1,
        const float* __restrict__ gin, const float* __restrict__ W2,
        const float* __restrict__ b2) {
    extern __shared__ float dyn[];
    float* Wt  = dyn;             // 64*68
    float* bsm = Wt + 64*68;      // 64
    float* Xs  = bsm + 64;        // 64*132
    int tid = threadIdx.x;

    if (blockIdx.x == 0 && blockIdx.y == 0 && tid == 0) {
        g_min_p_key = 0xFFFFFFFFu;
        g_min_d_key = 0xFFFFFFFFu;
    }

    int gside = blockIdx.x >= XBLK;
    int bx    = gside ? (blockIdx.x - XBLK) : blockIdx.x;
    int Ssz   = gside ? GSS : SS;
    const float* in   = gside ? gin : xin;
    const float* Wm   = gside ? W2 : W1;
    const float* bias = gside ? b2 : b1;

    for (int i = tid; i < 4096; i += 128) {
        int o = i >> 6, c = i & 63;
        Wt[c*68 + o] = Wm[i];
    }
    if (tid < 64) bsm[tid] = bias[tid];

    int b = blockIdx.y;
    size_t sbase = (size_t)b * CC * Ssz + (size_t)bx * 128;
    const float* src = in + sbase;
    for (int i = tid; i < 64*32; i += 128) {
        int c = i >> 5, sv = i & 31;
        float4 v = *(const float4*)(src + (size_t)c*Ssz + sv*4);
        *(float4*)&Xs[c*132 + sv*4] = v;
    }
    __syncthreads();

    int og = tid & 3;
    int sg = tid >> 2;
    float acc[16][4];
#pragma unroll
    for (int j = 0; j < 16; j++) {
        float bv = bsm[og*16 + j];
        acc[j][0]=bv; acc[j][1]=bv; acc[j][2]=bv; acc[j][3]=bv;
    }

#pragma unroll 4
    for (int c = 0; c < 64; c++) {
        float4 xv = *(const float4*)&Xs[c*132 + sg*4];
        float xk[4] = {xv.x, xv.y, xv.z, xv.w};
#pragma unroll
        for (int q = 0; q < 4; q++) {
            float4 wv = *(const float4*)&Wt[c*68 + og*16 + q*4];
            float wk[4] = {wv.x, wv.y, wv.z, wv.w};
#pragma unroll
            for (int jj = 0; jj < 4; jj++)
#pragma unroll
                for (int kk = 0; kk < 4; kk++)
                    acc[q*4+jj][kk] = fmaf(wk[jj], xk[kk], acc[q*4+jj][kk]);
        }
    }

    float* outp = (gside ? (float*)g_tgl : (float*)g_tx) + sbase;
#pragma unroll
    for (int j = 0; j < 16; j++) {
        int o = og*16 + j;
        float4 v = make_float4(acc[j][0], acc[j][1], acc[j][2], acc[j][3]);
        *(float4*)(outp + (size_t)o*Ssz + sg*4) = v;
    }
}

// ---- stats + fused trilinear upsample (R staged in-place in G tiles) -------
#define SD_SMEM (4*3328*4)
__global__ __launch_bounds__(256, 4) void k_stats_d() {
    extern __shared__ float dyn[];
    float* Ab = dyn;                 // [2][3328]
    float* Gb = dyn + 2*3328;        // [2][3328]  (R rows staged at [c*52+0..25])
    __shared__ float pp[256];
    __shared__ float rmin[8], rsum[8], pminw[8];
    int tid = threadIdx.x;

    // ---- stage 1: load A tiles; compute hw-interp rows R into G tiles ------
#pragma unroll
    for (int sj = 0; sj < 2; sj++) {
        int st = blockIdx.x*2 + sj;
        int b = st / HWn, hw = st - b*HWn;
        int h = hw / 48, w = hw - h*48;
        int kh = h >> 1, kw = w >> 1;
        int hf = (h & 1) ? (kh+1 > 23 ? 23 : kh+1) : (kh-1 < 0 ? 0 : kh-1);
        int wf = (w & 1) ? (kw+1 > 23 ? 23 : kw+1) : (kw-1 < 0 ? 0 : kw-1);
        const float* base = g_tgl + (size_t)b*CC*GSS;
        int o_nn = kh*576 + kw*24;
        int o_fn = hf*576 + kw*24;
        int o_nw = kh*576 + wf*24;
        int o_fw = hf*576 + wf*24;
        size_t gb = (size_t)b*CC*SS + (size_t)hw*LL;
        float* As = Ab + sj*3328;
        float* R  = Gb + sj*3328;       // R rows live at [c*52 + 0..25]

        for (int i = tid; i < 768; i += 256) {
            int c = i / 12, lv = i - c*12;
            size_t off = gb + (size_t)c*SS + lv*4;
            *(float4*)&As[c*52 + lv*4] = *(const float4*)(g_tx + off);
        }
        for (int i = tid; i < 384; i += 256) {
            int c = i / 6, q = i - c*6;
            const float* pc = base + (size_t)c*GSS + q*4;
            float4 a  = *(const float4*)(pc + o_nn);
            float4 bv = *(const float4*)(pc + o_fn);
            float4 cv = *(const float4*)(pc + o_nw);
            float4 dv = *(const float4*)(pc + o_fw);
            float r0 = 0.75f*(0.75f*a.x + 0.25f*bv.x) + 0.25f*(0.75f*cv.x + 0.25f*dv.x);
            float r1 = 0.75f*(0.75f*a.y + 0.25f*bv.y) + 0.25f*(0.75f*cv.y + 0.25f*dv.y);
            float r2 = 0.75f*(0.75f*a.z + 0.25f*bv.z) + 0.25f*(0.75f*cv.z + 0.25f*dv.z);
            float r3 = 0.75f*(0.75f*a.w + 0.25f*bv.w) + 0.25f*(0.75f*cv.w + 0.25f*dv.w);
            int idx = c*52 + 1 + q*4;
            R[idx+0] = r0; R[idx+1] = r1; R[idx+2] = r2; R[idx+3] = r3;
            if (q == 0) R[c*52]      = r0;   // l-clamp low
            if (q == 5) R[c*52 + 25] = r3;   // l-clamp high
        }
    }
    __syncthreads();

    // ---- stage 2: in-place expand R -> G (register staging, 2 thr/row) ----
    {
        int row = tid >> 1;              // 0..127 : (site, channel)
        int sl2 = row >> 6, c = row & 63;
        int hf = tid & 1;                // l-half: outputs hf*24 .. +23
        float* Gr = Gb + sl2*3328 + c*52;
        float r[14];
#pragma unroll
        for (int t = 0; t < 14; t++) r[t] = Gr[hf*12 + t];
        __syncthreads();                 // all R reads before any G writes
#pragma unroll
        for (int k = 0; k < 12; k++) {
            Gr[hf*24 + 2*k]     = 0.25f*r[k]   + 0.75f*r[k+1];
            Gr[hf*24 + 2*k + 1] = 0.75f*r[k+1] + 0.25f*r[k+2];
        }
    }
    __syncthreads();

    int sl = tid >> 7;          // site within block
    int s  = tid & 127;         // lane within site group
    const float* As = Ab + sl*3328;
    const float* Gs = Gb + sl*3328;

    // ---- p stats: 2 threads per channel-row, 24 elems each ----
    float pm = 3.402823466e38f;
    {
        int c = s >> 1, hf = s & 1;
        const float* Ar = &As[c*52 + hf*24];
        const float* Gr = &Gs[c*52 + hf*24];
        float ps = 0.f;
#pragma unroll
        for (int q = 0; q < 6; q++) {
            float4 a = *(const float4*)&Ar[q*4];
            float4 g = *(const float4*)&Gr[q*4];
            float t0 = a.x*g.x, t1 = a.y*g.y, t2 = a.z*g.z, t3 = a.w*g.w;
            ps += (t0+t1) + (t2+t3);
            pm = fminf(pm, fminf(fminf(t0,t1), fminf(t2,t3)));
        }
        pp[tid] = ps;
    }
#pragma unroll
    for (int off = 16; off; off >>= 1)
        pm = fminf(pm, __shfl_xor_sync(0xffffffffu, pm, off));
    if ((tid & 31) == 0) pminw[tid >> 5] = pm;

    // ---- raw = A*G^T : 4x8 tile per thread, interleaved mapping ----
    int ti = s >> 3;   // rows i = ti + 16*k, k=0..3
    int tj = s & 7;    // cols j = tj + 8*jj, jj=0..7

    float acc[4][8];
#pragma unroll
    for (int ii = 0; ii < 4; ii++)
#pragma unroll
        for (int jj = 0; jj < 8; jj++) acc[ii][jj] = 0.f;

    for (int l4 = 0; l4 < 12; l4++) {
        float4 av[4];
#pragma unroll
        for (int k = 0; k < 4; k++)
            av[k] = *(const float4*)&As[(ti + 16*k)*52 + l4*4];
#pragma unroll
        for (int jj = 0; jj < 8; jj++) {
            float4 gv = *(const float4*)&Gs[(tj + 8*jj)*52 + l4*4];
#pragma unroll
            for (int k = 0; k < 4; k++) {
                acc[k][jj] = fmaf(av[k].x, gv.x, acc[k][jj]);
                acc[k][jj] = fmaf(av[k].y, gv.y, acc[k][jj]);
                acc[k][jj] = fmaf(av[k].z, gv.z, acc[k][jj]);
                acc[k][jj] = fmaf(av[k].w, gv.w, acc[k][jj]);
            }
        }
    }

    float lmin = acc[0][0], lsum = 0.f;
#pragma unroll
    for (int ii = 0; ii < 4; ii++)
#pragma unroll
        for (int jj = 0; jj < 8; jj++) {
            lmin = fminf(lmin, acc[ii][jj]);
            lsum += acc[ii][jj];
        }
#pragma unroll
    for (int off = 16; off; off >>= 1) {
        lmin = fminf(lmin, __shfl_xor_sync(0xffffffffu, lmin, off));
        lsum += __shfl_xor_sync(0xffffffffu, lsum, off);
    }
    int wid = tid >> 5, lane = tid & 31;
    if (!lane) { rmin[wid] = lmin; rsum[wid] = lsum; }
    __syncthreads();

    // per-(b,c) p sums, transposed layout [bc][hw] for coalesced reduce
    if (s < 64) {
        int st = blockIdx.x*2 + sl;
        int b = st / HWn, hw = st - b*HWn;
        g_sitechan[(size_t)(b*64 + s)*HWn + hw] =
            pp[sl*128 + 2*s] + pp[sl*128 + 2*s + 1];
    }

    if (s == 0)   // tid 0 (site 0) and tid 128 (site 1)
        g_sitesum[blockIdx.x*2 + sl] =
            (rsum[sl*4+0] + rsum[sl*4+1]) + (rsum[sl*4+2] + rsum[sl*4+3]);

    if (tid == 0) {
        float m = fminf(fminf(fminf(rmin[0], rmin[1]), fminf(rmin[2], rmin[3])),
                        fminf(fminf(rmin[4], rmin[5]), fminf(rmin[6], rmin[7])));
        atomicMin(&g_min_d_key, fkey(m));
        float pmn = fminf(fminf(fminf(pminw[0], pminw[1]), fminf(pminw[2], pminw[3])),
                          fminf(fminf(pminw[4], pminw[5]), fminf(pminw[6], pminw[7])));
        atomicMin(&g_min_p_key, fkey(pmn));
    }
}

// ------- merged reductions: blocks 0..127 = per-(b,c) p; 128..129 = d -------
__global__ void k_reduce_all() {
    __shared__ float sh[256];
    int tid = threadIdx.x;
    if (blockIdx.x < 128) {
        int bc = blockIdx.x;
        const float* row = g_sitechan + (size_t)bc * HWn;
        float s = 0.f;
        for (int i = tid; i < HWn; i += 256)   // coalesced
            s += row[i];
        sh[tid] = s;
        __syncthreads();
        for (int st = 128; st > 0; st >>= 1) {
            if (tid < st) sh[tid] += sh[tid + st];
            __syncthreads();
        }
        if (tid == 0) {
            float m1 = funkey(g_min_p_key);
            g_inv1[bc] = 1.0f / (sh[0] - m1 * (float)SS);
        }
    } else {
        int b = blockIdx.x - 128;
        float s = 0.f;
        for (int i = tid; i < HWn; i += 256) s += g_sitesum[b * HWn + i];
        sh[tid] = s;
        __syncthreads();
        for (int st = 128; st > 0; st >>= 1) {
            if (tid < st) sh[tid] += sh[tid + st];
            __syncthreads();
        }
        if (tid == 0) {
            float m2 = funkey(g_min_d_key);
            g_inv2[b] = 1.0f / (sh[0] - m2 * 9437184.0f);
        }
    }
}

// -------- d (+ fused p): D = (G*(A^T X) - m2*colsum(X))*inv2 ----------------
#define KD_SMEM ((3328 + 3328 + 3264 + 32*26 + 48)*4)
__global__ __launch_bounds__(128, 5) void k_d(const float* __restrict__ x,
                                              float* __restrict__ outp,
                                              float* __restrict__ outd) {
    extern __shared__ float dyn[];
    float* As = dyn;            // 64*52   (phase1 input; becomes Ms)
    float* Ms = dyn;            // 48*52   overlay
    float* Xs = As + 3328;      // 64*52
    float* Gt = Xs + 3328;      // 48*68 (transposed, swizzled)
    float* Rh = Gt + 3264;      // 32*26  (half-channel interp rows)
    float* cs = Rh + 832;       // 48
    int tid = threadIdx.x;
    int site = blockIdx.x;
    int b = site / HWn, hw = site - b*HWn;
    size_t gb = (size_t)b*CC*SS + (size_t)hw*LL;

    // tap geometry (same as stats stage 1)
    int h = hw / 48, w = hw - h*48;
    int kh = h >> 1, kw = w >> 1;
    int hf = (h & 1) ? (kh+1 > 23 ? 23 : kh+1) : (kh-1 < 0 ? 0 : kh-1);
    int wf = (w & 1) ? (kw+1 > 23 ? 23 : kw+1) : (kw-1 < 0 ? 0 : kw-1);
    const float* base = g_tgl + (size_t)b*CC*GSS;
    int o_nn = kh*576 + kw*24;
    int o_fn = hf*576 + kw*24;
    int o_nw = kh*576 + wf*24;
    int o_fw = hf*576 + wf*24;

    float m1 = funkey(g_min_p_key);
#pragma unroll
    for (int half = 0; half < 2; half++) {
        int c0 = half * 32;
        // stage R for channels c0..c0+31 (bit-identical to stats arith)
        for (int i = tid; i < 192; i += 128) {
            int cl = i / 6, q = i - cl*6;
            const float* pc = base + (size_t)(c0 + cl)*GSS + q*4;
            float4 a  = *(const float4*)(pc + o_nn);
            float4 bv = *(const float4*)(pc + o_fn);
            float4 cv = *(const float4*)(pc + o_nw);
            float4 dv = *(const float4*)(pc + o_fw);
            float r0 = 0.75f*(0.75f*a.x + 0.25f*bv.x) + 0.25f*(0.75f*cv.x + 0.25f*dv.x);
            float r1 = 0.75f*(0.75f*a.y + 0.25f*bv.y) + 0.25f*(0.75f*cv.y + 0.25f*dv.y);
            float r2 = 0.75f*(0.75f*a.z + 0.25f*bv.z) + 0.25f*(0.75f*cv.z + 0.25f*dv.z);
            float r3 = 0.75f*(0.75f*a.w + 0.25f*bv.w) + 0.25f*(0.75f*cv.w + 0.25f*dv.w);
            int idx = cl*26 + 1 + q*4;
            Rh[idx+0] = r0; Rh[idx+1] = r1; Rh[idx+2] = r2; Rh[idx+3] = r3;
            if (q == 0) Rh[cl*26]      = r0;
            if (q == 5) Rh[cl*26 + 25] = r3;
        }
        __syncthreads();

        for (int i = tid; i < 384; i += 128) {
            int cl = i / 12, lv = i - cl*12;
            int c = c0 + cl;
            size_t off = gb + (size_t)c*SS + lv*4;
            float4 a  = __ldcs((const float4*)(g_tx + off));
            float4 xv = __ldcs((const float4*)(x + off));
            const float* Rr = Rh + cl*26 + 2*lv;
            float2 r01 = *(const float2*)(Rr);
            float2 r23 = *(const float2*)(Rr + 2);
            float4 gg;
            gg.x = 0.25f*r01.x + 0.75f*r01.y;
            gg.y = 0.75f*r01.y + 0.25f*r23.x;
            gg.z = 0.25f*r01.y + 0.75f*r23.x;
            gg.w = 0.75f*r23.x + 0.25f*r23.y;
            *(float4*)&As[c*52 + lv*4] = a;
            *(float4*)&Xs[c*52 + lv*4] = xv;
            {
                float gv[4] = {gg.x, gg.y, gg.z, gg.w};
#pragma unroll
                for (int q = 0; q < 4; q++) {
                    int row = lv*4 + q;
                    int colp = c ^ (8 * ((row >> 3) & 3));
                    Gt[row*68 + colp] = gv[q];
                }
            }
            float inv1 = g_inv1[b*64 + c];
            float4 o;
            o.x = (a.x*gg.x - m1) * xv.x * inv1;
            o.y = (a.y*gg.y - m1) * xv.y * inv1;
            o.z = (a.z*gg.z - m1) * xv.z * inv1;
            o.w = (a.w*gg.w - m1) * xv.w * inv1;
            __stcs((float4*)(outp + off), o);
        }
        __syncthreads();   // Rh reuse barrier (also finalizes tiles on half 1)
    }

    if (tid < 48) {
        float s = 0.f;
#pragma unroll 8
        for (int c = 0; c < 64; c++) s += Xs[c*52 + tid];
        cs[tid] = s;
    }

    // phase 1: M[lp][l] = sum_c A[c][lp] * X[c][l] (accumulate in registers)
    float p1acc[3][6];
    int p1ti = tid >> 3;
    int p1tj = tid & 7;
    {
#pragma unroll
        for (int ii = 0; ii < 3; ii++)
#pragma unroll
            for (int jj = 0; jj < 6; jj++) p1acc[ii][jj] = 0.f;

#pragma unroll 4
        for (int c = 0; c < 64; c++) {
            float a0 = As[c*52 + p1ti*3 + 0];
            float a1 = As[c*52 + p1ti*3 + 1];
            float a2 = As[c*52 + p1ti*3 + 2];
            float xv[6];
#pragma unroll
            for (int jj = 0; jj < 6; jj++) xv[jj] = Xs[c*52 + p1tj*6 + jj];
#pragma unroll
            for (int jj = 0; jj < 6; jj++) {
                p1acc[0][jj] = fmaf(a0, xv[jj], p1acc[0][jj]);
                p1acc[1][jj] = fmaf(a1, xv[jj], p1acc[1][jj]);
                p1acc[2][jj] = fmaf(a2, xv[jj], p1acc[2][jj]);
            }
        }
    }
    __syncthreads();   // all As reads done -> safe to overlay Ms

#pragma unroll
    for (int ii = 0; ii < 3; ii++)
#pragma unroll
        for (int jj = 0; jj < 6; jj++)
            Ms[(p1ti*3+ii)*52 + p1tj*6 + jj] = p1acc[ii][jj];
    __syncthreads();

    // phase 2: D[j][l] = sum_lp Gt[lp][j] * M[lp][l]
    float m2  = funkey(g_min_d_key);
    float inv = g_inv2[b];
    {
        int ti = tid >> 4;
        int tj = tid & 15;
        float acc[8][3];
#pragma unroll
        for (int k = 0; k < 8; k++)
#pragma unroll
            for (int m = 0; m < 3; m++) acc[k][m] = 0.f;

#pragma unroll 4
        for (int lp = 0; lp < 48; lp++) {
            int jbase = (ti*8) ^ (8 * ((lp >> 3) & 3));
            float4 gA = *(const float4*)&Gt[lp*68 + jbase];
            float4 gB = *(const float4*)&Gt[lp*68 + jbase + 4];
            float gk[8] = {gA.x,gA.y,gA.z,gA.w,gB.x,gB.y,gB.z,gB.w};
            float q0 = Ms[lp*52 + tj*3 + 0];
            float q1 = Ms[lp*52 + tj*3 + 1];
            float q2 = Ms[lp*52 + tj*3 + 2];
#pragma unroll
            for (int k = 0; k < 8; k++) {
                acc[k][0] = fmaf(gk[k], q0, acc[k][0]);
                acc[k][1] = fmaf(gk[k], q1, acc[k][1]);
                acc[k][2] = fmaf(gk[k], q2, acc[k][2]);
            }
        }

        float cc0 = cs[tj*3+0], cc1 = cs[tj*3+1], cc2 = cs[tj*3+2];
#pragma unroll
        for (int k = 0; k < 8; k++) {
            int j = ti*8 + k;
            size_t ob = gb + (size_t)j*SS + tj*3;
            __stcs(outd + ob + 0, (acc[k][0] - m2*cc0) * inv);
            __stcs(outd + ob + 1, (acc[k][1] - m2*cc1) * inv);
            __stcs(outd + ob + 2, (acc[k][2] - m2*cc2) * inv);
        }
    }
}

// ---------------- launch ----------------------------------------------------
extern "C" void kernel_launch(void* const* d_in, const int* in_sizes, int n_in,
                              void* d_out, int out_size) {
    const float* x  = (const float*)d_in[0];
    const float* g  = (const float*)d_in[1];
    const float* W1 = (const float*)d_in[2];
    const float* b1 = (const float*)d_in[3];
    const float* W2 = (const float*)d_in[4];
    const float* b2 = (const float*)d_in[5];

    float* out  = (float*)d_out;
    float* outp = out;
    float* outd = out + (size_t)TOTAL;

    cudaFuncSetAttribute(k_chanmix, cudaFuncAttributeMaxDynamicSharedMemorySize, CM_SMEM);
    cudaFuncSetAttribute(k_stats_d, cudaFuncAttributeMaxDynamicSharedMemorySize, SD_SMEM);
    cudaFuncSetAttribute(k_d,       cudaFuncAttributeMaxDynamicSharedMemorySize, KD_SMEM);

    { dim3 gc(XBLK + GSS/128, BB);
      k_chanmix<<<gc, 128, CM_SMEM>>>(x, W1, b1, g, W2, b2); }

    k_stats_d<<<NSITES/2, 256, SD_SMEM>>>();
    k_reduce_all<<<130, 256>>>();

    k_d<<<NSITES, 128, KD_SMEM>>>(x, outp, outd);
}